// round 1
// baseline (speedup 1.0000x reference)
#include <cuda_runtime.h>
#include <math.h>

// Problem constants
#define BSZ  4096
#define INF  2048
#define OUTF 2048
#define NG   8192      // 4*OUT
#define KSEG 2048      // every GEMM segment has K = 2048

// Scratch: raw gate pre-activations [B, 4*OUT] (peephole i/f terms already folded in)
__device__ float g_gates[(size_t)BSZ * NG];   // 128 MiB

// ---------------------------------------------------------------------------
// Packed fp32x2 FMA (Blackwell): doubles fp32 FMA throughput vs scalar FFMA.
// ---------------------------------------------------------------------------
__device__ __forceinline__ void fma2(float2& c, float2 a, float2 b) {
    unsigned long long uc = *reinterpret_cast<unsigned long long*>(&c);
    unsigned long long ua = *reinterpret_cast<unsigned long long*>(&a);
    unsigned long long ub = *reinterpret_cast<unsigned long long*>(&b);
    asm("fma.rn.f32x2 %0, %1, %2, %0;" : "+l"(uc) : "l"(ua), "l"(ub));
    c = *reinterpret_cast<float2*>(&uc);
}

__device__ __forceinline__ float sigf(float x) {
    return 1.0f / (1.0f + expf(-x));
}

// ---------------------------------------------------------------------------
// Shared tile-MAC over one K=2048 segment.
// Tile: 128(M) x 128(N) x 16(K). 256 threads, 8x8 outputs/thread.
// As/Bs stored K-major with stride 132 (keeps 16B alignment, kills bank
// conflicts on both the transposed stores and the float4 compute loads).
// ---------------------------------------------------------------------------
__device__ __forceinline__ void run_segment(
    const float* __restrict__ A,     // [M, 2048] row-major, full matrix
    const float* __restrict__ Bp,    // [*, 2048] row-major, already offset to n0 row
    int m0, int tid, int tx, int ty,
    float (&As)[16][132], float (&Bs)[16][132],
    float2 (&acc)[8][4])
{
    for (int kt = 0; kt < KSEG; kt += 16) {
        #pragma unroll
        for (int it = 0; it < 2; ++it) {
            int t  = tid + it * 256;      // 0..511
            int r  = t >> 2;              // 0..127 (tile row)
            int k4 = (t & 3) << 2;        // 0,4,8,12
            float4 av = *reinterpret_cast<const float4*>(
                A + (size_t)(m0 + r) * KSEG + kt + k4);
            As[k4 + 0][r] = av.x; As[k4 + 1][r] = av.y;
            As[k4 + 2][r] = av.z; As[k4 + 3][r] = av.w;
            float4 bv = *reinterpret_cast<const float4*>(
                Bp + (size_t)r * KSEG + kt + k4);
            Bs[k4 + 0][r] = bv.x; Bs[k4 + 1][r] = bv.y;
            Bs[k4 + 2][r] = bv.z; Bs[k4 + 3][r] = bv.w;
        }
        __syncthreads();
        #pragma unroll
        for (int k = 0; k < 16; ++k) {
            float4 a0 = *reinterpret_cast<const float4*>(&As[k][ty * 8]);
            float4 a1 = *reinterpret_cast<const float4*>(&As[k][ty * 8 + 4]);
            float4 b0 = *reinterpret_cast<const float4*>(&Bs[k][tx * 8]);
            float4 b1 = *reinterpret_cast<const float4*>(&Bs[k][tx * 8 + 4]);
            float  am[8] = {a0.x, a0.y, a0.z, a0.w, a1.x, a1.y, a1.z, a1.w};
            float2 bm[4];
            bm[0] = make_float2(b0.x, b0.y); bm[1] = make_float2(b0.z, b0.w);
            bm[2] = make_float2(b1.x, b1.y); bm[3] = make_float2(b1.z, b1.w);
            #pragma unroll
            for (int i = 0; i < 8; ++i) {
                float2 ad = make_float2(am[i], am[i]);
                #pragma unroll
                for (int j = 0; j < 4; ++j) fma2(acc[i][j], ad, bm[j]);
            }
        }
        __syncthreads();
    }
}

// ---------------------------------------------------------------------------
// GEMM1: gates[B, 8192] = x@w_ih^T + hx@w_hh^T (+ cx@w_pi^T / cx@w_pf^T on
// the first half of N, folded as a 3rd K-segment) + b_ih + b_hh.
// grid = (64, 32), block = 256.
// ---------------------------------------------------------------------------
__global__ __launch_bounds__(256, 2)
void gemm_gates_kernel(const float* __restrict__ x,  const float* __restrict__ hx,
                       const float* __restrict__ cx,
                       const float* __restrict__ w_ih, const float* __restrict__ w_hh,
                       const float* __restrict__ w_pi, const float* __restrict__ w_pf,
                       const float* __restrict__ b_ih, const float* __restrict__ b_hh)
{
    __shared__ float As[16][132];
    __shared__ float Bs[16][132];

    const int tid = threadIdx.x;
    const int m0  = blockIdx.y * 128;
    const int n0  = blockIdx.x * 128;
    const int tx  = tid & 15;
    const int ty  = tid >> 4;

    float2 acc[8][4];
    #pragma unroll
    for (int i = 0; i < 8; ++i)
        #pragma unroll
        for (int j = 0; j < 4; ++j) acc[i][j] = make_float2(0.f, 0.f);

    run_segment(x,  w_ih + (size_t)n0 * KSEG, m0, tid, tx, ty, As, Bs, acc);
    run_segment(hx, w_hh + (size_t)n0 * KSEG, m0, tid, tx, ty, As, Bs, acc);
    if (n0 < 2 * OUTF) {
        const float* wp = (n0 < OUTF) ? (w_pi + (size_t)n0 * KSEG)
                                      : (w_pf + (size_t)(n0 - OUTF) * KSEG);
        run_segment(cx, wp, m0, tid, tx, ty, As, Bs, acc);
    }

    // epilogue: biases + store
    float2 bias[4];
    #pragma unroll
    for (int j = 0; j < 4; ++j) {
        int col = n0 + tx * 8 + j * 2;
        bias[j] = make_float2(b_ih[col]     + b_hh[col],
                              b_ih[col + 1] + b_hh[col + 1]);
    }
    #pragma unroll
    for (int i = 0; i < 8; ++i) {
        int row = m0 + ty * 8 + i;
        float* gp = g_gates + (size_t)row * NG + n0 + tx * 8;
        #pragma unroll
        for (int j = 0; j < 4; ++j) {
            float2 v = acc[i][j];
            v.x += bias[j].x;
            v.y += bias[j].y;
            *reinterpret_cast<float2*>(gp + j * 2) = v;
        }
    }
}

// ---------------------------------------------------------------------------
// Elementwise cell update: cy = forcoff*sigmoid(f)*cx + incoff*sigmoid(i)*tanh(g)
// Writes cy directly into the second half of d_out.
// ---------------------------------------------------------------------------
__global__ __launch_bounds__(256)
void cell_kernel(const float* __restrict__ cx,
                 const float* __restrict__ td0, const float* __restrict__ td1,
                 const float* __restrict__ aS,  const float* __restrict__ bS,
                 float* __restrict__ cy_out)
{
    size_t idx4 = (size_t)blockIdx.x * blockDim.x + threadIdx.x;
    const size_t total4 = (size_t)BSZ * OUTF / 4;
    if (idx4 >= total4) return;
    int row = (int)(idx4 / (OUTF / 4));
    int c   = (int)(idx4 % (OUTF / 4)) * 4;

    float a = aS[0], b = bS[0];
    float forc = a * expf(-b * td0[row]);
    float inc  = a * expf(-b * td1[row]);

    const float* grow = g_gates + (size_t)row * NG;
    float4 ig  = *reinterpret_cast<const float4*>(grow + c);
    float4 fg  = *reinterpret_cast<const float4*>(grow + OUTF + c);
    float4 gg  = *reinterpret_cast<const float4*>(grow + 2 * OUTF + c);
    float4 cxv = *reinterpret_cast<const float4*>(cx + (size_t)row * OUTF + c);

    float4 r;
    r.x = forc * sigf(fg.x) * cxv.x + inc * sigf(ig.x) * tanhf(gg.x);
    r.y = forc * sigf(fg.y) * cxv.y + inc * sigf(ig.y) * tanhf(gg.y);
    r.z = forc * sigf(fg.z) * cxv.z + inc * sigf(ig.z) * tanhf(gg.z);
    r.w = forc * sigf(fg.w) * cxv.w + inc * sigf(ig.w) * tanhf(gg.w);
    *reinterpret_cast<float4*>(cy_out + (size_t)row * OUTF + c) = r;
}

// ---------------------------------------------------------------------------
// GEMM3: O = cy @ w_po^T, fused epilogue: hy = sigmoid(gate_o + O) * tanh(cy)
// grid = (16, 32), block = 256.
// ---------------------------------------------------------------------------
__global__ __launch_bounds__(256, 2)
void gemm_out_kernel(const float* __restrict__ cy,    // [B, OUT] (second half of d_out)
                     const float* __restrict__ w_po,
                     float* __restrict__ hy)           // [B, OUT] (first half of d_out)
{
    __shared__ float As[16][132];
    __shared__ float Bs[16][132];

    const int tid = threadIdx.x;
    const int m0  = blockIdx.y * 128;
    const int n0  = blockIdx.x * 128;
    const int tx  = tid & 15;
    const int ty  = tid >> 4;

    float2 acc[8][4];
    #pragma unroll
    for (int i = 0; i < 8; ++i)
        #pragma unroll
        for (int j = 0; j < 4; ++j) acc[i][j] = make_float2(0.f, 0.f);

    run_segment(cy, w_po + (size_t)n0 * KSEG, m0, tid, tx, ty, As, Bs, acc);

    #pragma unroll
    for (int i = 0; i < 8; ++i) {
        int row = m0 + ty * 8 + i;
        const float* gorow = g_gates + (size_t)row * NG + 3 * OUTF;
        const float* cyrow = cy + (size_t)row * OUTF;
        float*       hyrow = hy + (size_t)row * OUTF;
        #pragma unroll
        for (int j = 0; j < 4; ++j) {
            int col = n0 + tx * 8 + j * 2;
            float2 go  = *reinterpret_cast<const float2*>(gorow + col);
            float2 cyv = *reinterpret_cast<const float2*>(cyrow + col);
            float2 r;
            r.x = sigf(go.x + acc[i][j].x) * tanhf(cyv.x);
            r.y = sigf(go.y + acc[i][j].y) * tanhf(cyv.y);
            *reinterpret_cast<float2*>(hyrow + col) = r;
        }
    }
}

// ---------------------------------------------------------------------------
extern "C" void kernel_launch(void* const* d_in, const int* in_sizes, int n_in,
                              void* d_out, int out_size)
{
    (void)in_sizes; (void)n_in; (void)out_size;
    const float* x    = (const float*)d_in[0];
    const float* td0  = (const float*)d_in[1];
    const float* td1  = (const float*)d_in[2];
    const float* hx   = (const float*)d_in[3];
    const float* cx   = (const float*)d_in[4];
    const float* w_ih = (const float*)d_in[5];
    const float* w_hh = (const float*)d_in[6];
    const float* w_pi = (const float*)d_in[7];
    const float* w_pf = (const float*)d_in[8];
    const float* w_po = (const float*)d_in[9];
    const float* b_ih = (const float*)d_in[10];
    const float* b_hh = (const float*)d_in[11];
    const float* aS   = (const float*)d_in[12];
    const float* bS   = (const float*)d_in[13];

    float* out = (float*)d_out;
    float* hy  = out;                               // [B, OUT]
    float* cy  = out + (size_t)BSZ * OUTF;          // [B, OUT]

    gemm_gates_kernel<<<dim3(NG / 128, BSZ / 128), 256>>>(
        x, hx, cx, w_ih, w_hh, w_pi, w_pf, b_ih, b_hh);

    cell_kernel<<<(BSZ * OUTF / 4 + 255) / 256, 256>>>(
        cx, td0, td1, aS, bS, cy);

    gemm_out_kernel<<<dim3(OUTF / 128, BSZ / 128), 256>>>(
        cy, w_po, hy);
}

// round 3
// speedup vs baseline: 2.6680x; 2.6680x over previous
#include <cuda_runtime.h>
#include <cuda_bf16.h>
#include <cstdint>
#include <math.h>

#define BSZ  4096
#define OUTF 2048
#define NG   8192
#define KDIM 2048

// fp32 gate pre-activations scratch [B, 4*OUT]
__device__ float g_gates[(size_t)BSZ * NG];   // 128 MiB

__device__ __forceinline__ uint32_t smem_u32(const void* p) {
    uint32_t a;
    asm("{ .reg .u64 t; cvta.to.shared.u64 t, %1; cvt.u32.u64 %0, t; }" : "=r"(a) : "l"(p));
    return a;
}
__device__ __forceinline__ float sigf(float x) { return 1.0f / (1.0f + expf(-x)); }

// SW128 swizzle on byte offsets within a 1024B-aligned tile (8 rows x 128B atom)
__device__ __forceinline__ uint32_t sw128(uint32_t off) {
    return off ^ ((off >> 3) & 0x70);
}

// ldmatrix x4 (non-transposed, b16)
__device__ __forceinline__ void ldsm4(uint32_t addr, uint32_t* r) {
    asm volatile("ldmatrix.sync.aligned.m8n8.x4.shared.b16 {%0,%1,%2,%3}, [%4];"
        : "=r"(r[0]), "=r"(r[1]), "=r"(r[2]), "=r"(r[3]) : "r"(addr));
}

// bf16 HMMA m16n8k16, fp32 accumulate
__device__ __forceinline__ void mma16816(float* d, const uint32_t* a, const uint32_t* b) {
    asm volatile(
        "mma.sync.aligned.m16n8k16.row.col.f32.bf16.bf16.f32 "
        "{%0,%1,%2,%3}, {%4,%5,%6,%7}, {%8,%9}, {%0,%1,%2,%3};"
        : "+f"(d[0]), "+f"(d[1]), "+f"(d[2]), "+f"(d[3])
        : "r"(a[0]), "r"(a[1]), "r"(a[2]), "r"(a[3]), "r"(b[0]), "r"(b[1]));
}

// ---------------- SMEM layout ----------------
// header 1024B: bias[128] floats at offset 0 (gates kernel only)
// stage (64KB): Ahi 16K | Alo 16K | Bhi 16K | Blo 16K   (tiles 128 rows x 128B, SW128)
#define HDR       1024
#define T_AHI     0
#define T_ALO     16384
#define T_BHI     32768
#define T_BLO     49152
#define STAGE_SZ  65536
#define SMEM_TOTAL (HDR + 2 * STAGE_SZ)   // 132096

// convert one float4 (4 elems) to hi/lo bf16, store 8B each at swizzled offset
__device__ __forceinline__ void cvt8(char* hi, char* lo, uint32_t off, float4 v) {
    uint32_t sw = sw128(off);
    __nv_bfloat162 h0 = __floats2bfloat162_rn(v.x, v.y);
    __nv_bfloat162 h1 = __floats2bfloat162_rn(v.z, v.w);
    float2 f0 = __bfloat1622float2(h0);
    float2 f1 = __bfloat1622float2(h1);
    __nv_bfloat162 l0 = __floats2bfloat162_rn(v.x - f0.x, v.y - f0.y);
    __nv_bfloat162 l1 = __floats2bfloat162_rn(v.z - f1.x, v.w - f1.y);
    uint2 hb = make_uint2(*reinterpret_cast<uint32_t*>(&h0), *reinterpret_cast<uint32_t*>(&h1));
    uint2 lb = make_uint2(*reinterpret_cast<uint32_t*>(&l0), *reinterpret_cast<uint32_t*>(&l1));
    *reinterpret_cast<uint2*>(hi + sw) = hb;
    *reinterpret_cast<uint2*>(lo + sw) = lb;
}

// Load one K=64 chunk (A: 128 rows, B: 128 rows, fp32) into registers.
__device__ __forceinline__ void load_gmem(const float* __restrict__ Ab,
                                          const float* __restrict__ Bb,
                                          int tid, float4* regs) {
    #pragma unroll
    for (int it = 0; it < 4; ++it) {
        int idx = tid + it * 512;
        int r = idx >> 4, c4 = idx & 15;
        regs[it] = *reinterpret_cast<const float4*>(Ab + (size_t)r * KDIM + c4 * 4);
    }
    #pragma unroll
    for (int it = 0; it < 4; ++it) {
        int idx = tid + it * 512;
        int r = idx >> 4, c4 = idx & 15;
        regs[4 + it] = *reinterpret_cast<const float4*>(Bb + (size_t)r * KDIM + c4 * 4);
    }
}

// Convert registers -> hi/lo bf16 swizzled SMEM stage.
__device__ __forceinline__ void cvt_sts(char* stage, int tid, const float4* regs) {
    #pragma unroll
    for (int it = 0; it < 4; ++it) {
        int idx = tid + it * 512;
        int r = idx >> 4, c4 = idx & 15;
        cvt8(stage + T_AHI, stage + T_ALO, (uint32_t)(r * 128 + c4 * 8), regs[it]);
    }
    #pragma unroll
    for (int it = 0; it < 4; ++it) {
        int idx = tid + it * 512;
        int r = idx >> 4, c4 = idx & 15;
        cvt8(stage + T_BHI, stage + T_BLO, (uint32_t)(r * 128 + c4 * 8), regs[4 + it]);
    }
}

// Compute one K=64 chunk: warp tile 32(M) x 32(N), 3-term split.
// acc[mt][n8][4], mt in 0..1 (m16 tiles), n8 in 0..3.
__device__ __forceinline__ void compute_chunk(uint32_t stage_addr, int wm, int wn,
                                              int lane, float (&acc)[2][4][4]) {
    const uint32_t ahi = stage_addr + T_AHI;
    const uint32_t alo = stage_addr + T_ALO;
    const uint32_t bhi = stage_addr + T_BHI;
    const uint32_t blo = stage_addr + T_BLO;
    const int a_m = lane % 16;
    const int a_k = (lane / 16) * 8;
    const int b_n = (lane / 16) * 8 + (lane % 8);
    const int b_k = ((lane / 8) % 2) * 8;

    #pragma unroll
    for (int kk = 0; kk < 4; ++kk) {
        uint32_t Ah[2][4], Al[2][4], Bh[2][4], Bl[2][4];
        #pragma unroll
        for (int mt = 0; mt < 2; ++mt) {
            uint32_t off = sw128((uint32_t)((wm + mt * 16 + a_m) * 128 + kk * 32 + a_k * 2));
            ldsm4(ahi + off, Ah[mt]);
            ldsm4(alo + off, Al[mt]);
        }
        #pragma unroll
        for (int nt = 0; nt < 2; ++nt) {
            uint32_t off = sw128((uint32_t)((wn + nt * 16 + b_n) * 128 + kk * 32 + b_k * 2));
            ldsm4(bhi + off, Bh[nt]);
            ldsm4(blo + off, Bl[nt]);
        }
        #pragma unroll
        for (int mt = 0; mt < 2; ++mt)
            #pragma unroll
            for (int nt = 0; nt < 2; ++nt)
                #pragma unroll
                for (int h = 0; h < 2; ++h) {
                    float* d = acc[mt][nt * 2 + h];
                    mma16816(d, Ah[mt], &Bh[nt][h * 2]);   // hi*hi
                    mma16816(d, Ah[mt], &Bl[nt][h * 2]);   // hi*lo
                    mma16816(d, Al[mt], &Bh[nt][h * 2]);   // lo*hi
                }
    }
}

// ---------------------------------------------------------------------------
// GEMM1: gates[B, 8192] = x@w_ih^T + hx@w_hh^T (+ cx@w_pi^T / cx@w_pf^T) + biases
// grid = (32 m-tiles, 64 n-tiles), block = 512. CTA tile 128x128.
// ---------------------------------------------------------------------------
__global__ __launch_bounds__(512, 1)
void gemm_gates(const float* __restrict__ x,  const float* __restrict__ hx,
                const float* __restrict__ cx,
                const float* __restrict__ w_ih, const float* __restrict__ w_hh,
                const float* __restrict__ w_pi, const float* __restrict__ w_pf,
                const float* __restrict__ b_ih, const float* __restrict__ b_hh)
{
    extern __shared__ char sm[];
    const int tid  = threadIdx.x;
    const int wid  = tid >> 5;
    const int lane = tid & 31;
    const int m0   = blockIdx.x * 128;
    const int n0   = blockIdx.y * 128;
    const int wm   = (wid % 4) * 32;
    const int wn   = (wid / 4) * 32;

    float* bsum = reinterpret_cast<float*>(sm);
    if (tid < 128) bsum[tid] = b_ih[n0 + tid] + b_hh[n0 + tid];

    const uint32_t smb = smem_u32(sm);
    const int nseg = (n0 < 2 * OUTF) ? 3 : 2;
    const float* segA[3];
    const float* segB[3];
    segA[0] = x;  segB[0] = w_ih + (size_t)n0 * KDIM;
    segA[1] = hx; segB[1] = w_hh + (size_t)n0 * KDIM;
    segA[2] = cx;
    segB[2] = (n0 < OUTF) ? (w_pi + (size_t)n0 * KDIM)
                          : (w_pf + (size_t)(n0 - OUTF) * KDIM);

    float acc[2][4][4];
    #pragma unroll
    for (int i = 0; i < 2; ++i)
        #pragma unroll
        for (int j = 0; j < 4; ++j)
            #pragma unroll
            for (int k = 0; k < 4; ++k) acc[i][j][k] = 0.f;

    const int nch = nseg * 32;
    float4 regs[8];

    load_gmem(segA[0] + (size_t)m0 * KDIM, segB[0], tid, regs);
    cvt_sts(sm + HDR, tid, regs);
    __syncthreads();

    for (int c = 0; c < nch; ++c) {
        if (c + 1 < nch) {
            const int seg = (c + 1) >> 5;
            const int kc  = ((c + 1) & 31) << 6;
            load_gmem(segA[seg] + (size_t)m0 * KDIM + kc, segB[seg] + kc, tid, regs);
        }
        compute_chunk(smb + HDR + (c & 1) * STAGE_SZ, wm, wn, lane, acc);
        if (c + 1 < nch)
            cvt_sts(sm + HDR + ((c + 1) & 1) * STAGE_SZ, tid, regs);
        __syncthreads();
    }

    // epilogue: bias + store fp32
    #pragma unroll
    for (int mt = 0; mt < 2; ++mt) {
        #pragma unroll
        for (int n8 = 0; n8 < 4; ++n8) {
            int lcol = wn + n8 * 8 + (lane % 4) * 2;
            float bx0 = bsum[lcol], bx1 = bsum[lcol + 1];
            int r0 = m0 + wm + mt * 16 + lane / 4;
            float* g0 = g_gates + (size_t)r0 * NG + n0 + lcol;
            float* g1 = g_gates + (size_t)(r0 + 8) * NG + n0 + lcol;
            float2 v0 = make_float2(acc[mt][n8][0] + bx0, acc[mt][n8][1] + bx1);
            float2 v1 = make_float2(acc[mt][n8][2] + bx0, acc[mt][n8][3] + bx1);
            *reinterpret_cast<float2*>(g0) = v0;
            *reinterpret_cast<float2*>(g1) = v1;
        }
    }
}

// ---------------------------------------------------------------------------
// Cell update: cy = a*exp(-b*td0)*sig(f)*cx + a*exp(-b*td1)*sig(i)*tanh(g)
// ---------------------------------------------------------------------------
__global__ __launch_bounds__(256)
void cell_kernel(const float* __restrict__ cx,
                 const float* __restrict__ td0, const float* __restrict__ td1,
                 const float* __restrict__ aS,  const float* __restrict__ bS,
                 float* __restrict__ cy_out)
{
    size_t idx4 = (size_t)blockIdx.x * blockDim.x + threadIdx.x;
    const size_t total4 = (size_t)BSZ * OUTF / 4;
    if (idx4 >= total4) return;
    int row = (int)(idx4 / (OUTF / 4));
    int c   = (int)(idx4 % (OUTF / 4)) * 4;

    float a = aS[0], b = bS[0];
    float forc = a * expf(-b * td0[row]);
    float inc  = a * expf(-b * td1[row]);

    const float* grow = g_gates + (size_t)row * NG;
    float4 ig  = *reinterpret_cast<const float4*>(grow + c);
    float4 fg  = *reinterpret_cast<const float4*>(grow + OUTF + c);
    float4 gg  = *reinterpret_cast<const float4*>(grow + 2 * OUTF + c);
    float4 cxv = *reinterpret_cast<const float4*>(cx + (size_t)row * OUTF + c);

    float4 r;
    r.x = forc * sigf(fg.x) * cxv.x + inc * sigf(ig.x) * tanhf(gg.x);
    r.y = forc * sigf(fg.y) * cxv.y + inc * sigf(ig.y) * tanhf(gg.y);
    r.z = forc * sigf(fg.z) * cxv.z + inc * sigf(ig.z) * tanhf(gg.z);
    r.w = forc * sigf(fg.w) * cxv.w + inc * sigf(ig.w) * tanhf(gg.w);
    *reinterpret_cast<float4*>(cy_out + (size_t)row * OUTF + c) = r;
}

// ---------------------------------------------------------------------------
// GEMM3: O = cy @ w_po^T ; hy = sigmoid(gate_o + O) * tanh(cy)
// grid = (32 m-tiles, 16 n-tiles), block = 512.
// ---------------------------------------------------------------------------
__global__ __launch_bounds__(512, 1)
void gemm_out(const float* __restrict__ cy, const float* __restrict__ w_po,
              float* __restrict__ hy)
{
    extern __shared__ char sm[];
    const int tid  = threadIdx.x;
    const int wid  = tid >> 5;
    const int lane = tid & 31;
    const int m0   = blockIdx.x * 128;
    const int n0   = blockIdx.y * 128;
    const int wm   = (wid % 4) * 32;
    const int wn   = (wid / 4) * 32;

    const uint32_t smb = smem_u32(sm);
    const float* Ab = cy + (size_t)m0 * KDIM;
    const float* Bb = w_po + (size_t)n0 * KDIM;

    float acc[2][4][4];
    #pragma unroll
    for (int i = 0; i < 2; ++i)
        #pragma unroll
        for (int j = 0; j < 4; ++j)
            #pragma unroll
            for (int k = 0; k < 4; ++k) acc[i][j][k] = 0.f;

    const int nch = 32;
    float4 regs[8];

    load_gmem(Ab, Bb, tid, regs);
    cvt_sts(sm + HDR, tid, regs);
    __syncthreads();

    for (int c = 0; c < nch; ++c) {
        if (c + 1 < nch) {
            const int kc = (c + 1) << 6;
            load_gmem(Ab + kc, Bb + kc, tid, regs);
        }
        compute_chunk(smb + HDR + (c & 1) * STAGE_SZ, wm, wn, lane, acc);
        if (c + 1 < nch)
            cvt_sts(sm + HDR + ((c + 1) & 1) * STAGE_SZ, tid, regs);
        __syncthreads();
    }

    // fused epilogue
    #pragma unroll
    for (int mt = 0; mt < 2; ++mt) {
        #pragma unroll
        for (int n8 = 0; n8 < 4; ++n8) {
            int col = n0 + wn + n8 * 8 + (lane % 4) * 2;
            #pragma unroll
            for (int half = 0; half < 2; ++half) {
                int row = m0 + wm + mt * 16 + lane / 4 + half * 8;
                const float* gorow = g_gates + (size_t)row * NG + 3 * OUTF + col;
                const float* cyrow = cy + (size_t)row * OUTF + col;
                float*       hyrow = hy + (size_t)row * OUTF + col;
                float2 go  = *reinterpret_cast<const float2*>(gorow);
                float2 cyv = *reinterpret_cast<const float2*>(cyrow);
                float2 r;
                r.x = sigf(go.x + acc[mt][n8][half * 2 + 0]) * tanhf(cyv.x);
                r.y = sigf(go.y + acc[mt][n8][half * 2 + 1]) * tanhf(cyv.y);
                *reinterpret_cast<float2*>(hyrow) = r;
            }
        }
    }
}

// ---------------------------------------------------------------------------
extern "C" void kernel_launch(void* const* d_in, const int* in_sizes, int n_in,
                              void* d_out, int out_size)
{
    (void)in_sizes; (void)n_in; (void)out_size;
    const float* x    = (const float*)d_in[0];
    const float* td0  = (const float*)d_in[1];
    const float* td1  = (const float*)d_in[2];
    const float* hx   = (const float*)d_in[3];
    const float* cx   = (const float*)d_in[4];
    const float* w_ih = (const float*)d_in[5];
    const float* w_hh = (const float*)d_in[6];
    const float* w_pi = (const float*)d_in[7];
    const float* w_pf = (const float*)d_in[8];
    const float* w_po = (const float*)d_in[9];
    const float* b_ih = (const float*)d_in[10];
    const float* b_hh = (const float*)d_in[11];
    const float* aS   = (const float*)d_in[12];
    const float* bS   = (const float*)d_in[13];

    float* out = (float*)d_out;
    float* hy  = out;                        // [B, OUT]
    float* cy  = out + (size_t)BSZ * OUTF;   // [B, OUT]

    cudaFuncSetAttribute(gemm_gates, cudaFuncAttributeMaxDynamicSharedMemorySize, SMEM_TOTAL);
    cudaFuncSetAttribute(gemm_out,   cudaFuncAttributeMaxDynamicSharedMemorySize, SMEM_TOTAL);

    gemm_gates<<<dim3(BSZ / 128, NG / 128), 512, SMEM_TOTAL>>>(
        x, hx, cx, w_ih, w_hh, w_pi, w_pf, b_ih, b_hh);

    cell_kernel<<<(BSZ * OUTF / 4 + 255) / 256, 256>>>(
        cx, td0, td1, aS, bS, cy);

    gemm_out<<<dim3(BSZ / 128, OUTF / 128), 512, SMEM_TOTAL>>>(
        cy, w_po, hy);
}

// round 4
// speedup vs baseline: 2.9915x; 1.1213x over previous
#include <cuda_runtime.h>
#include <cuda_bf16.h>
#include <cstdint>
#include <math.h>

#define BSZ  4096
#define OUTF 2048
#define NG   8192
#define KDIM 2048

// fp32 gate pre-activations scratch [B, 4*OUT]
__device__ float g_gates[(size_t)BSZ * NG];   // 128 MiB

__device__ __forceinline__ uint32_t smem_u32(const void* p) {
    uint32_t a;
    asm("{ .reg .u64 t; cvta.to.shared.u64 t, %1; cvt.u32.u64 %0, t; }" : "=r"(a) : "l"(p));
    return a;
}
__device__ __forceinline__ float sigf(float x) { return 1.0f / (1.0f + expf(-x)); }

// SW128 swizzle on byte offsets within a 1024B-aligned region
__device__ __forceinline__ uint32_t sw128(uint32_t off) {
    return off ^ ((off >> 3) & 0x70);
}

// fp32 -> tf32 round-to-nearest (keeps bits in a .b32)
__device__ __forceinline__ uint32_t f2tf32(float f) {
    uint32_t r;
    asm("cvt.rna.tf32.f32 %0, %1;" : "=r"(r) : "f"(f));
    return r;
}

// ldmatrix x4 (b16 path; 8x8 b16 tile == 8x4 fp32 tile)
__device__ __forceinline__ void ldsm4(uint32_t addr, uint32_t* r) {
    asm volatile("ldmatrix.sync.aligned.m8n8.x4.shared.b16 {%0,%1,%2,%3}, [%4];"
        : "=r"(r[0]), "=r"(r[1]), "=r"(r[2]), "=r"(r[3]) : "r"(addr));
}

// tf32 MMA m16n8k8, fp32 accumulate
__device__ __forceinline__ void mma1688(float* d, const uint32_t* a, uint32_t b0, uint32_t b1) {
    asm volatile(
        "mma.sync.aligned.m16n8k8.row.col.f32.tf32.tf32.f32 "
        "{%0,%1,%2,%3}, {%4,%5,%6,%7}, {%8,%9}, {%0,%1,%2,%3};"
        : "+f"(d[0]), "+f"(d[1]), "+f"(d[2]), "+f"(d[3])
        : "r"(a[0]), "r"(a[1]), "r"(a[2]), "r"(a[3]), "r"(b0), "r"(b1));
}

// ---------------- SMEM layout ----------------
// header 1024B: bias[128] floats (gates kernel only)
// stage (64KB): A 32KB | B 32KB.
// Each operand tile = 2 subtiles of [128 rows x 32 fp32-cols] = 128 x 128B, SW128.
#define HDR       1024
#define T_A       0
#define T_B       32768
#define SUB_SZ    16384
#define STAGE_SZ  65536
#define SMEM_TOTAL (HDR + 2 * STAGE_SZ)   // 132096

// Load one K=64 chunk (A: 128 rows, B: 128 rows, fp32) into registers.
__device__ __forceinline__ void load_gmem(const float* __restrict__ Ab,
                                          const float* __restrict__ Bb,
                                          int tid, float4* regs) {
    #pragma unroll
    for (int it = 0; it < 4; ++it) {
        int idx = tid + it * 512;
        int r = idx >> 4, c4 = idx & 15;
        regs[it] = *reinterpret_cast<const float4*>(Ab + (size_t)r * KDIM + c4 * 4);
    }
    #pragma unroll
    for (int it = 0; it < 4; ++it) {
        int idx = tid + it * 512;
        int r = idx >> 4, c4 = idx & 15;
        regs[4 + it] = *reinterpret_cast<const float4*>(Bb + (size_t)r * KDIM + c4 * 4);
    }
}

// tf32-round + store one float4 at swizzled offset. c4 = float4 column (0..15).
__device__ __forceinline__ void sts_tf32(char* base, int r, int c4, float4 v) {
    uint32_t off = (uint32_t)(c4 >> 3) * SUB_SZ
                 + sw128((uint32_t)(r * 128 + (c4 & 7) * 16));
    uint4 u = make_uint4(f2tf32(v.x), f2tf32(v.y), f2tf32(v.z), f2tf32(v.w));
    *reinterpret_cast<uint4*>(base + off) = u;
}

__device__ __forceinline__ void cvt_sts(char* stage, int tid, const float4* regs) {
    #pragma unroll
    for (int it = 0; it < 4; ++it) {
        int idx = tid + it * 512;
        sts_tf32(stage + T_A, idx >> 4, idx & 15, regs[it]);
    }
    #pragma unroll
    for (int it = 0; it < 4; ++it) {
        int idx = tid + it * 512;
        sts_tf32(stage + T_B, idx >> 4, idx & 15, regs[4 + it]);
    }
}

// Compute one K=64 chunk (8 k8-steps): warp tile 32(M) x 32(N).
// acc[mt][n8][4], mt in 0..1 (m16), n8 in 0..3.
__device__ __forceinline__ void compute_chunk(uint32_t stage_addr, int wm, int wn,
                                              int lane, float (&acc)[2][4][4]) {
    // ldmatrix x4 lane -> (tile = lane/8): row = base + (tile&1)*8 + lane%8,
    // fp32 col-group = (tile>>1)*4. Tiles: (r0: k0-3 lo-rows, r1: k0-3 hi-rows,
    // r2: k4-7 lo-rows, r3: k4-7 hi-rows)
    const int lrow = ((lane >> 3) & 1) * 8 + (lane & 7);
    const int lcol = (lane >> 4) * 4;                     // fp32 cols within k8

    const uint32_t a_base = stage_addr + T_A;
    const uint32_t b_base = stage_addr + T_B;

    #pragma unroll
    for (int s = 0; s < 8; ++s) {
        const uint32_t sub = (uint32_t)(s >> 2) * SUB_SZ;
        const int kloc = (s & 3) * 8;                     // fp32 col base in subtile

        uint32_t Af[2][4], Bf[2][4];
        #pragma unroll
        for (int mt = 0; mt < 2; ++mt) {
            uint32_t off = sw128((uint32_t)((wm + mt * 16 + lrow) * 128 + (kloc + lcol) * 4));
            ldsm4(a_base + sub + off, Af[mt]);
        }
        #pragma unroll
        for (int ng = 0; ng < 2; ++ng) {
            uint32_t off = sw128((uint32_t)((wn + ng * 16 + lrow) * 128 + (kloc + lcol) * 4));
            ldsm4(b_base + sub + off, Bf[ng]);
        }
        #pragma unroll
        for (int mt = 0; mt < 2; ++mt)
            #pragma unroll
            for (int n8 = 0; n8 < 4; ++n8)
                mma1688(acc[mt][n8], Af[mt],
                        Bf[n8 >> 1][n8 & 1], Bf[n8 >> 1][(n8 & 1) + 2]);
    }
}

// ---------------------------------------------------------------------------
// GEMM1: gates[B, 8192] = x@w_ih^T + hx@w_hh^T (+ cx@w_pi^T / cx@w_pf^T) + biases
// grid = (32 m-tiles, 64 n-tiles), block = 512. CTA tile 128x128.
// ---------------------------------------------------------------------------
__global__ __launch_bounds__(512, 1)
void gemm_gates(const float* __restrict__ x,  const float* __restrict__ hx,
                const float* __restrict__ cx,
                const float* __restrict__ w_ih, const float* __restrict__ w_hh,
                const float* __restrict__ w_pi, const float* __restrict__ w_pf,
                const float* __restrict__ b_ih, const float* __restrict__ b_hh)
{
    extern __shared__ char sm[];
    const int tid  = threadIdx.x;
    const int wid  = tid >> 5;
    const int lane = tid & 31;
    const int m0   = blockIdx.x * 128;
    const int n0   = blockIdx.y * 128;
    const int wm   = (wid % 4) * 32;
    const int wn   = (wid / 4) * 32;

    float* bsum = reinterpret_cast<float*>(sm);
    if (tid < 128) bsum[tid] = b_ih[n0 + tid] + b_hh[n0 + tid];

    const uint32_t smb = smem_u32(sm);
    const int nseg = (n0 < 2 * OUTF) ? 3 : 2;
    const float* segA[3];
    const float* segB[3];
    segA[0] = x;  segB[0] = w_ih + (size_t)n0 * KDIM;
    segA[1] = hx; segB[1] = w_hh + (size_t)n0 * KDIM;
    segA[2] = cx;
    segB[2] = (n0 < OUTF) ? (w_pi + (size_t)n0 * KDIM)
                          : (w_pf + (size_t)(n0 - OUTF) * KDIM);

    float acc[2][4][4];
    #pragma unroll
    for (int i = 0; i < 2; ++i)
        #pragma unroll
        for (int j = 0; j < 4; ++j)
            #pragma unroll
            for (int k = 0; k < 4; ++k) acc[i][j][k] = 0.f;

    const int nch = nseg * 32;
    float4 regs[8];

    load_gmem(segA[0] + (size_t)m0 * KDIM, segB[0], tid, regs);
    cvt_sts(sm + HDR, tid, regs);
    __syncthreads();

    for (int c = 0; c < nch; ++c) {
        if (c + 1 < nch) {
            const int seg = (c + 1) >> 5;
            const int kc  = ((c + 1) & 31) << 6;
            load_gmem(segA[seg] + (size_t)m0 * KDIM + kc, segB[seg] + kc, tid, regs);
        }
        compute_chunk(smb + HDR + (c & 1) * STAGE_SZ, wm, wn, lane, acc);
        if (c + 1 < nch)
            cvt_sts(sm + HDR + ((c + 1) & 1) * STAGE_SZ, tid, regs);
        __syncthreads();
    }

    // epilogue: bias + store fp32
    #pragma unroll
    for (int mt = 0; mt < 2; ++mt) {
        #pragma unroll
        for (int n8 = 0; n8 < 4; ++n8) {
            int lcol = wn + n8 * 8 + (lane % 4) * 2;
            float bx0 = bsum[lcol], bx1 = bsum[lcol + 1];
            int r0 = m0 + wm + mt * 16 + lane / 4;
            float* g0 = g_gates + (size_t)r0 * NG + n0 + lcol;
            float* g1 = g_gates + (size_t)(r0 + 8) * NG + n0 + lcol;
            float2 v0 = make_float2(acc[mt][n8][0] + bx0, acc[mt][n8][1] + bx1);
            float2 v1 = make_float2(acc[mt][n8][2] + bx0, acc[mt][n8][3] + bx1);
            *reinterpret_cast<float2*>(g0) = v0;
            *reinterpret_cast<float2*>(g1) = v1;
        }
    }
}

// ---------------------------------------------------------------------------
// Cell update: cy = a*exp(-b*td0)*sig(f)*cx + a*exp(-b*td1)*sig(i)*tanh(g)
// ---------------------------------------------------------------------------
__global__ __launch_bounds__(256)
void cell_kernel(const float* __restrict__ cx,
                 const float* __restrict__ td0, const float* __restrict__ td1,
                 const float* __restrict__ aS,  const float* __restrict__ bS,
                 float* __restrict__ cy_out)
{
    size_t idx4 = (size_t)blockIdx.x * blockDim.x + threadIdx.x;
    const size_t total4 = (size_t)BSZ * OUTF / 4;
    if (idx4 >= total4) return;
    int row = (int)(idx4 / (OUTF / 4));
    int c   = (int)(idx4 % (OUTF / 4)) * 4;

    float a = aS[0], b = bS[0];
    float forc = a * expf(-b * td0[row]);
    float inc  = a * expf(-b * td1[row]);

    const float* grow = g_gates + (size_t)row * NG;
    float4 ig  = *reinterpret_cast<const float4*>(grow + c);
    float4 fg  = *reinterpret_cast<const float4*>(grow + OUTF + c);
    float4 gg  = *reinterpret_cast<const float4*>(grow + 2 * OUTF + c);
    float4 cxv = *reinterpret_cast<const float4*>(cx + (size_t)row * OUTF + c);

    float4 r;
    r.x = forc * sigf(fg.x) * cxv.x + inc * sigf(ig.x) * tanhf(gg.x);
    r.y = forc * sigf(fg.y) * cxv.y + inc * sigf(ig.y) * tanhf(gg.y);
    r.z = forc * sigf(fg.z) * cxv.z + inc * sigf(ig.z) * tanhf(gg.z);
    r.w = forc * sigf(fg.w) * cxv.w + inc * sigf(ig.w) * tanhf(gg.w);
    *reinterpret_cast<float4*>(cy_out + (size_t)row * OUTF + c) = r;
}

// ---------------------------------------------------------------------------
// GEMM3: O = cy @ w_po^T ; hy = sigmoid(gate_o + O) * tanh(cy)
// grid = (32 m-tiles, 16 n-tiles), block = 512.
// ---------------------------------------------------------------------------
__global__ __launch_bounds__(512, 1)
void gemm_out(const float* __restrict__ cy, const float* __restrict__ w_po,
              float* __restrict__ hy)
{
    extern __shared__ char sm[];
    const int tid  = threadIdx.x;
    const int wid  = tid >> 5;
    const int lane = tid & 31;
    const int m0   = blockIdx.x * 128;
    const int n0   = blockIdx.y * 128;
    const int wm   = (wid % 4) * 32;
    const int wn   = (wid / 4) * 32;

    const uint32_t smb = smem_u32(sm);
    const float* Ab = cy + (size_t)m0 * KDIM;
    const float* Bb = w_po + (size_t)n0 * KDIM;

    float acc[2][4][4];
    #pragma unroll
    for (int i = 0; i < 2; ++i)
        #pragma unroll
        for (int j = 0; j < 4; ++j)
            #pragma unroll
            for (int k = 0; k < 4; ++k) acc[i][j][k] = 0.f;

    const int nch = 32;
    float4 regs[8];

    load_gmem(Ab, Bb, tid, regs);
    cvt_sts(sm + HDR, tid, regs);
    __syncthreads();

    for (int c = 0; c < nch; ++c) {
        if (c + 1 < nch) {
            const int kc = (c + 1) << 6;
            load_gmem(Ab + kc, Bb + kc, tid, regs);
        }
        compute_chunk(smb + HDR + (c & 1) * STAGE_SZ, wm, wn, lane, acc);
        if (c + 1 < nch)
            cvt_sts(sm + HDR + ((c + 1) & 1) * STAGE_SZ, tid, regs);
        __syncthreads();
    }

    // fused epilogue
    #pragma unroll
    for (int mt = 0; mt < 2; ++mt) {
        #pragma unroll
        for (int n8 = 0; n8 < 4; ++n8) {
            int col = n0 + wn + n8 * 8 + (lane % 4) * 2;
            #pragma unroll
            for (int half = 0; half < 2; ++half) {
                int row = m0 + wm + mt * 16 + lane / 4 + half * 8;
                const float* gorow = g_gates + (size_t)row * NG + 3 * OUTF + col;
                const float* cyrow = cy + (size_t)row * OUTF + col;
                float*       hyrow = hy + (size_t)row * OUTF + col;
                float2 go  = *reinterpret_cast<const float2*>(gorow);
                float2 cyv = *reinterpret_cast<const float2*>(cyrow);
                float2 r;
                r.x = sigf(go.x + acc[mt][n8][half * 2 + 0]) * tanhf(cyv.x);
                r.y = sigf(go.y + acc[mt][n8][half * 2 + 1]) * tanhf(cyv.y);
                *reinterpret_cast<float2*>(hyrow) = r;
            }
        }
    }
}

// ---------------------------------------------------------------------------
extern "C" void kernel_launch(void* const* d_in, const int* in_sizes, int n_in,
                              void* d_out, int out_size)
{
    (void)in_sizes; (void)n_in; (void)out_size;
    const float* x    = (const float*)d_in[0];
    const float* td0  = (const float*)d_in[1];
    const float* td1  = (const float*)d_in[2];
    const float* hx   = (const float*)d_in[3];
    const float* cx   = (const float*)d_in[4];
    const float* w_ih = (const float*)d_in[5];
    const float* w_hh = (const float*)d_in[6];
    const float* w_pi = (const float*)d_in[7];
    const float* w_pf = (const float*)d_in[8];
    const float* w_po = (const float*)d_in[9];
    const float* b_ih = (const float*)d_in[10];
    const float* b_hh = (const float*)d_in[11];
    const float* aS   = (const float*)d_in[12];
    const float* bS   = (const float*)d_in[13];

    float* out = (float*)d_out;
    float* hy  = out;                        // [B, OUT]
    float* cy  = out + (size_t)BSZ * OUTF;   // [B, OUT]

    cudaFuncSetAttribute(gemm_gates, cudaFuncAttributeMaxDynamicSharedMemorySize, SMEM_TOTAL);
    cudaFuncSetAttribute(gemm_out,   cudaFuncAttributeMaxDynamicSharedMemorySize, SMEM_TOTAL);

    gemm_gates<<<dim3(BSZ / 128, NG / 128), 512, SMEM_TOTAL>>>(
        x, hx, cx, w_ih, w_hh, w_pi, w_pf, b_ih, b_hh);

    cell_kernel<<<(BSZ * OUTF / 4 + 255) / 256, 256>>>(
        cx, td0, td1, aS, bS, cy);

    gemm_out<<<dim3(BSZ / 128, OUTF / 128), 512, SMEM_TOTAL>>>(
        cy, w_po, hy);
}

// round 5
// speedup vs baseline: 5.3090x; 1.7747x over previous
#include <cuda_runtime.h>
#include <cuda_fp16.h>
#include <cstdint>
#include <math.h>

#define BSZ  4096
#define OUTF 2048
#define NG   8192
#define KDIM 2048

// fp32 gate pre-activations scratch [B, 4*OUT]
__device__ float g_gates[(size_t)BSZ * NG];   // 128 MiB

__device__ __forceinline__ uint32_t smem_u32(const void* p) {
    uint32_t a;
    asm("{ .reg .u64 t; cvta.to.shared.u64 t, %1; cvt.u32.u64 %0, t; }" : "=r"(a) : "l"(p));
    return a;
}
__device__ __forceinline__ float sigf(float x) { return 1.0f / (1.0f + expf(-x)); }

// SW128 swizzle on byte offsets within a 1024B-aligned region
__device__ __forceinline__ uint32_t sw128(uint32_t off) {
    return off ^ ((off >> 3) & 0x70);
}

// ldmatrix x4 (non-transposed, b16)
__device__ __forceinline__ void ldsm4(uint32_t addr, uint32_t* r) {
    asm volatile("ldmatrix.sync.aligned.m8n8.x4.shared.b16 {%0,%1,%2,%3}, [%4];"
        : "=r"(r[0]), "=r"(r[1]), "=r"(r[2]), "=r"(r[3]) : "r"(addr));
}

// fp16 HMMA m16n8k16, fp32 accumulate
__device__ __forceinline__ void mma16816(float* d, const uint32_t* a, const uint32_t* b) {
    asm volatile(
        "mma.sync.aligned.m16n8k16.row.col.f32.f16.f16.f32 "
        "{%0,%1,%2,%3}, {%4,%5,%6,%7}, {%8,%9}, {%0,%1,%2,%3};"
        : "+f"(d[0]), "+f"(d[1]), "+f"(d[2]), "+f"(d[3])
        : "r"(a[0]), "r"(a[1]), "r"(a[2]), "r"(a[3]), "r"(b[0]), "r"(b[1]));
}

// ---------------- SMEM layout ----------------
// header 1024B: bias[128] floats (gates kernel only)
// stage (32KB): A 16KB | B 16KB  (tiles 128 rows x 128B fp16, SW128)
#define HDR       1024
#define T_A       0
#define T_B       16384
#define STAGE_SZ  32768
#define SMEM_TOTAL (HDR + 2 * STAGE_SZ)   // 66560

// convert one float4 to 4 fp16, store 8B at swizzled offset
__device__ __forceinline__ void cvt4h(char* base, uint32_t off, float4 v) {
    uint32_t sw = sw128(off);
    __half2 h0 = __floats2half2_rn(v.x, v.y);
    __half2 h1 = __floats2half2_rn(v.z, v.w);
    uint2 u = make_uint2(*reinterpret_cast<uint32_t*>(&h0),
                         *reinterpret_cast<uint32_t*>(&h1));
    *reinterpret_cast<uint2*>(base + sw) = u;
}

// Load one K=64 chunk (A: 128 rows, B: 128 rows, fp32) into registers.
__device__ __forceinline__ void load_gmem(const float* __restrict__ Ab,
                                          const float* __restrict__ Bb,
                                          int tid, float4* regs) {
    #pragma unroll
    for (int it = 0; it < 4; ++it) {
        int idx = tid + it * 512;
        int r = idx >> 4, c4 = idx & 15;
        regs[it] = *reinterpret_cast<const float4*>(Ab + (size_t)r * KDIM + c4 * 4);
    }
    #pragma unroll
    for (int it = 0; it < 4; ++it) {
        int idx = tid + it * 512;
        int r = idx >> 4, c4 = idx & 15;
        regs[4 + it] = *reinterpret_cast<const float4*>(Bb + (size_t)r * KDIM + c4 * 4);
    }
}

// Convert registers -> fp16 swizzled SMEM stage.
__device__ __forceinline__ void cvt_sts(char* stage, int tid, const float4* regs) {
    #pragma unroll
    for (int it = 0; it < 4; ++it) {
        int idx = tid + it * 512;
        int r = idx >> 4, c4 = idx & 15;
        cvt4h(stage + T_A, (uint32_t)(r * 128 + c4 * 8), regs[it]);
    }
    #pragma unroll
    for (int it = 0; it < 4; ++it) {
        int idx = tid + it * 512;
        int r = idx >> 4, c4 = idx & 15;
        cvt4h(stage + T_B, (uint32_t)(r * 128 + c4 * 8), regs[4 + it]);
    }
}

// Compute one K=64 chunk (4 k16 steps): warp tile 32(M) x 32(N).
// acc[mt][n8][4], mt in 0..1 (m16), n8 in 0..3.
__device__ __forceinline__ void compute_chunk(uint32_t stage_addr, int wm, int wn,
                                              int lane, float (&acc)[2][4][4]) {
    const uint32_t a_base = stage_addr + T_A;
    const uint32_t b_base = stage_addr + T_B;
    const int a_m = lane % 16;
    const int a_k = (lane / 16) * 8;
    const int b_n = (lane / 16) * 8 + (lane % 8);
    const int b_k = ((lane / 8) % 2) * 8;

    #pragma unroll
    for (int kk = 0; kk < 4; ++kk) {
        uint32_t Ah[2][4], Bh[2][4];
        #pragma unroll
        for (int mt = 0; mt < 2; ++mt) {
            uint32_t off = sw128((uint32_t)((wm + mt * 16 + a_m) * 128 + kk * 32 + a_k * 2));
            ldsm4(a_base + off, Ah[mt]);
        }
        #pragma unroll
        for (int nt = 0; nt < 2; ++nt) {
            uint32_t off = sw128((uint32_t)((wn + nt * 16 + b_n) * 128 + kk * 32 + b_k * 2));
            ldsm4(b_base + off, Bh[nt]);
        }
        #pragma unroll
        for (int mt = 0; mt < 2; ++mt)
            #pragma unroll
            for (int nt = 0; nt < 2; ++nt)
                #pragma unroll
                for (int h = 0; h < 2; ++h)
                    mma16816(acc[mt][nt * 2 + h], Ah[mt], &Bh[nt][h * 2]);
    }
}

// ---------------------------------------------------------------------------
// GEMM1: gates[B, 8192] = x@w_ih^T + hx@w_hh^T (+ cx@w_pi^T / cx@w_pf^T) + biases
// grid = (32 m-tiles, 64 n-tiles), block = 512. CTA tile 128x128.
// ---------------------------------------------------------------------------
__global__ __launch_bounds__(512, 1)
void gemm_gates(const float* __restrict__ x,  const float* __restrict__ hx,
                const float* __restrict__ cx,
                const float* __restrict__ w_ih, const float* __restrict__ w_hh,
                const float* __restrict__ w_pi, const float* __restrict__ w_pf,
                const float* __restrict__ b_ih, const float* __restrict__ b_hh)
{
    extern __shared__ char sm[];
    const int tid  = threadIdx.x;
    const int wid  = tid >> 5;
    const int lane = tid & 31;
    const int m0   = blockIdx.x * 128;
    const int n0   = blockIdx.y * 128;
    const int wm   = (wid % 4) * 32;
    const int wn   = (wid / 4) * 32;

    float* bsum = reinterpret_cast<float*>(sm);
    if (tid < 128) bsum[tid] = b_ih[n0 + tid] + b_hh[n0 + tid];

    const uint32_t smb = smem_u32(sm);
    const int nseg = (n0 < 2 * OUTF) ? 3 : 2;
    const float* segA[3];
    const float* segB[3];
    segA[0] = x;  segB[0] = w_ih + (size_t)n0 * KDIM;
    segA[1] = hx; segB[1] = w_hh + (size_t)n0 * KDIM;
    segA[2] = cx;
    segB[2] = (n0 < OUTF) ? (w_pi + (size_t)n0 * KDIM)
                          : (w_pf + (size_t)(n0 - OUTF) * KDIM);

    float acc[2][4][4];
    #pragma unroll
    for (int i = 0; i < 2; ++i)
        #pragma unroll
        for (int j = 0; j < 4; ++j)
            #pragma unroll
            for (int k = 0; k < 4; ++k) acc[i][j][k] = 0.f;

    const int nch = nseg * 32;
    float4 regs[8];

    load_gmem(segA[0] + (size_t)m0 * KDIM, segB[0], tid, regs);
    cvt_sts(sm + HDR, tid, regs);
    __syncthreads();

    for (int c = 0; c < nch; ++c) {
        if (c + 1 < nch) {
            const int seg = (c + 1) >> 5;
            const int kc  = ((c + 1) & 31) << 6;
            load_gmem(segA[seg] + (size_t)m0 * KDIM + kc, segB[seg] + kc, tid, regs);
        }
        compute_chunk(smb + HDR + (c & 1) * STAGE_SZ, wm, wn, lane, acc);
        if (c + 1 < nch)
            cvt_sts(sm + HDR + ((c + 1) & 1) * STAGE_SZ, tid, regs);
        __syncthreads();
    }

    // epilogue: bias + store fp32
    #pragma unroll
    for (int mt = 0; mt < 2; ++mt) {
        #pragma unroll
        for (int n8 = 0; n8 < 4; ++n8) {
            int lcol = wn + n8 * 8 + (lane % 4) * 2;
            float bx0 = bsum[lcol], bx1 = bsum[lcol + 1];
            int r0 = m0 + wm + mt * 16 + lane / 4;
            float* g0 = g_gates + (size_t)r0 * NG + n0 + lcol;
            float* g1 = g_gates + (size_t)(r0 + 8) * NG + n0 + lcol;
            float2 v0 = make_float2(acc[mt][n8][0] + bx0, acc[mt][n8][1] + bx1);
            float2 v1 = make_float2(acc[mt][n8][2] + bx0, acc[mt][n8][3] + bx1);
            *reinterpret_cast<float2*>(g0) = v0;
            *reinterpret_cast<float2*>(g1) = v1;
        }
    }
}

// ---------------------------------------------------------------------------
// Cell update: cy = a*exp(-b*td0)*sig(f)*cx + a*exp(-b*td1)*sig(i)*tanh(g)
// ---------------------------------------------------------------------------
__global__ __launch_bounds__(256)
void cell_kernel(const float* __restrict__ cx,
                 const float* __restrict__ td0, const float* __restrict__ td1,
                 const float* __restrict__ aS,  const float* __restrict__ bS,
                 float* __restrict__ cy_out)
{
    size_t idx4 = (size_t)blockIdx.x * blockDim.x + threadIdx.x;
    const size_t total4 = (size_t)BSZ * OUTF / 4;
    if (idx4 >= total4) return;
    int row = (int)(idx4 / (OUTF / 4));
    int c   = (int)(idx4 % (OUTF / 4)) * 4;

    float a = aS[0], b = bS[0];
    float forc = a * expf(-b * td0[row]);
    float inc  = a * expf(-b * td1[row]);

    const float* grow = g_gates + (size_t)row * NG;
    float4 ig  = *reinterpret_cast<const float4*>(grow + c);
    float4 fg  = *reinterpret_cast<const float4*>(grow + OUTF + c);
    float4 gg  = *reinterpret_cast<const float4*>(grow + 2 * OUTF + c);
    float4 cxv = *reinterpret_cast<const float4*>(cx + (size_t)row * OUTF + c);

    float4 r;
    r.x = forc * sigf(fg.x) * cxv.x + inc * sigf(ig.x) * tanhf(gg.x);
    r.y = forc * sigf(fg.y) * cxv.y + inc * sigf(ig.y) * tanhf(gg.y);
    r.z = forc * sigf(fg.z) * cxv.z + inc * sigf(ig.z) * tanhf(gg.z);
    r.w = forc * sigf(fg.w) * cxv.w + inc * sigf(ig.w) * tanhf(gg.w);
    *reinterpret_cast<float4*>(cy_out + (size_t)row * OUTF + c) = r;
}

// ---------------------------------------------------------------------------
// GEMM3: O = cy @ w_po^T ; hy = sigmoid(gate_o + O) * tanh(cy)
// grid = (32 m-tiles, 16 n-tiles), block = 512.
// ---------------------------------------------------------------------------
__global__ __launch_bounds__(512, 1)
void gemm_out(const float* __restrict__ cy, const float* __restrict__ w_po,
              float* __restrict__ hy)
{
    extern __shared__ char sm[];
    const int tid  = threadIdx.x;
    const int wid  = tid >> 5;
    const int lane = tid & 31;
    const int m0   = blockIdx.x * 128;
    const int n0   = blockIdx.y * 128;
    const int wm   = (wid % 4) * 32;
    const int wn   = (wid / 4) * 32;

    const uint32_t smb = smem_u32(sm);
    const float* Ab = cy + (size_t)m0 * KDIM;
    const float* Bb = w_po + (size_t)n0 * KDIM;

    float acc[2][4][4];
    #pragma unroll
    for (int i = 0; i < 2; ++i)
        #pragma unroll
        for (int j = 0; j < 4; ++j)
            #pragma unroll
            for (int k = 0; k < 4; ++k) acc[i][j][k] = 0.f;

    const int nch = 32;
    float4 regs[8];

    load_gmem(Ab, Bb, tid, regs);
    cvt_sts(sm + HDR, tid, regs);
    __syncthreads();

    for (int c = 0; c < nch; ++c) {
        if (c + 1 < nch) {
            const int kc = (c + 1) << 6;
            load_gmem(Ab + kc, Bb + kc, tid, regs);
        }
        compute_chunk(smb + HDR + (c & 1) * STAGE_SZ, wm, wn, lane, acc);
        if (c + 1 < nch)
            cvt_sts(sm + HDR + ((c + 1) & 1) * STAGE_SZ, tid, regs);
        __syncthreads();
    }

    // fused epilogue
    #pragma unroll
    for (int mt = 0; mt < 2; ++mt) {
        #pragma unroll
        for (int n8 = 0; n8 < 4; ++n8) {
            int col = n0 + wn + n8 * 8 + (lane % 4) * 2;
            #pragma unroll
            for (int half = 0; half < 2; ++half) {
                int row = m0 + wm + mt * 16 + lane / 4 + half * 8;
                const float* gorow = g_gates + (size_t)row * NG + 3 * OUTF + col;
                const float* cyrow = cy + (size_t)row * OUTF + col;
                float*       hyrow = hy + (size_t)row * OUTF + col;
                float2 go  = *reinterpret_cast<const float2*>(gorow);
                float2 cyv = *reinterpret_cast<const float2*>(cyrow);
                float2 r;
                r.x = sigf(go.x + acc[mt][n8][half * 2 + 0]) * tanhf(cyv.x);
                r.y = sigf(go.y + acc[mt][n8][half * 2 + 1]) * tanhf(cyv.y);
                *reinterpret_cast<float2*>(hyrow) = r;
            }
        }
    }
}

// ---------------------------------------------------------------------------
extern "C" void kernel_launch(void* const* d_in, const int* in_sizes, int n_in,
                              void* d_out, int out_size)
{
    (void)in_sizes; (void)n_in; (void)out_size;
    const float* x    = (const float*)d_in[0];
    const float* td0  = (const float*)d_in[1];
    const float* td1  = (const float*)d_in[2];
    const float* hx   = (const float*)d_in[3];
    const float* cx   = (const float*)d_in[4];
    const float* w_ih = (const float*)d_in[5];
    const float* w_hh = (const float*)d_in[6];
    const float* w_pi = (const float*)d_in[7];
    const float* w_pf = (const float*)d_in[8];
    const float* w_po = (const float*)d_in[9];
    const float* b_ih = (const float*)d_in[10];
    const float* b_hh = (const float*)d_in[11];
    const float* aS   = (const float*)d_in[12];
    const float* bS   = (const float*)d_in[13];

    float* out = (float*)d_out;
    float* hy  = out;                        // [B, OUT]
    float* cy  = out + (size_t)BSZ * OUTF;   // [B, OUT]

    cudaFuncSetAttribute(gemm_gates, cudaFuncAttributeMaxDynamicSharedMemorySize, SMEM_TOTAL);
    cudaFuncSetAttribute(gemm_out,   cudaFuncAttributeMaxDynamicSharedMemorySize, SMEM_TOTAL);

    gemm_gates<<<dim3(BSZ / 128, NG / 128), 512, SMEM_TOTAL>>>(
        x, hx, cx, w_ih, w_hh, w_pi, w_pf, b_ih, b_hh);

    cell_kernel<<<(BSZ * OUTF / 4 + 255) / 256, 256>>>(
        cx, td0, td1, aS, bS, cy);

    gemm_out<<<dim3(BSZ / 128, OUTF / 128), 512, SMEM_TOTAL>>>(
        cy, w_po, hy);
}

// round 6
// speedup vs baseline: 7.7356x; 1.4571x over previous
#include <cuda_runtime.h>
#include <cuda_fp16.h>
#include <cstdint>
#include <math.h>

#define BSZ  4096
#define OUTF 2048
#define NG   8192
#define KDIM 2048

// fp32 gate pre-activations scratch [B, 4*OUT]
__device__ float g_gates[(size_t)BSZ * NG];   // 128 MiB

// fp16 copies (filled by prologue converts / cell kernel)
__device__ __half g_xh [(size_t)BSZ * KDIM];
__device__ __half g_hxh[(size_t)BSZ * KDIM];
__device__ __half g_cxh[(size_t)BSZ * KDIM];
__device__ __half g_cyh[(size_t)BSZ * KDIM];
__device__ __half g_wih[(size_t)NG * KDIM];
__device__ __half g_whh[(size_t)NG * KDIM];
__device__ __half g_wp [(size_t)2 * OUTF * KDIM];   // w_pi rows then w_pf rows
__device__ __half g_wpo[(size_t)OUTF * KDIM];

__device__ __forceinline__ uint32_t smem_u32(const void* p) {
    uint32_t a;
    asm("{ .reg .u64 t; cvta.to.shared.u64 t, %1; cvt.u32.u64 %0, t; }" : "=r"(a) : "l"(p));
    return a;
}
__device__ __forceinline__ float sigf(float x) { return 1.0f / (1.0f + expf(-x)); }

__device__ __forceinline__ uint32_t sw128(uint32_t off) {
    return off ^ ((off >> 3) & 0x70);
}

__device__ __forceinline__ void ldsm4(uint32_t addr, uint32_t* r) {
    asm volatile("ldmatrix.sync.aligned.m8n8.x4.shared.b16 {%0,%1,%2,%3}, [%4];"
        : "=r"(r[0]), "=r"(r[1]), "=r"(r[2]), "=r"(r[3]) : "r"(addr));
}

__device__ __forceinline__ void mma16816(float* d, const uint32_t* a, const uint32_t* b) {
    asm volatile(
        "mma.sync.aligned.m16n8k16.row.col.f32.f16.f16.f32 "
        "{%0,%1,%2,%3}, {%4,%5,%6,%7}, {%8,%9}, {%0,%1,%2,%3};"
        : "+f"(d[0]), "+f"(d[1]), "+f"(d[2]), "+f"(d[3])
        : "r"(a[0]), "r"(a[1]), "r"(a[2]), "r"(a[3]), "r"(b[0]), "r"(b[1]));
}

__device__ __forceinline__ void cpa16(uint32_t dst, const void* src) {
    asm volatile("cp.async.cg.shared.global [%0], [%1], 16;" :: "r"(dst), "l"(src));
}
#define CP_COMMIT() asm volatile("cp.async.commit_group;" ::: "memory")
#define CP_WAIT1()  asm volatile("cp.async.wait_group 1;"  ::: "memory")
#define CP_WAIT0()  asm volatile("cp.async.wait_group 0;"  ::: "memory")

// ---------------- SMEM layout ----------------
// header 1024B: bias[128] floats (gates kernel only)
// stage (48KB): A 32KB (256 rows x 128B) | B 16KB (128 rows x 128B), fp16, SW128
#define HDR       1024
#define T_A       0
#define T_B       32768
#define STAGE_SZ  49152
#define SMEM_TOTAL (HDR + 2 * STAGE_SZ)   // 99328

// async-load one K=64 chunk: A 256 rows, B 128 rows (fp16 global, row stride KDIM)
__device__ __forceinline__ void load_chunk(const __half* __restrict__ Ab,
                                           const __half* __restrict__ Bb,
                                           uint32_t stage, int tid) {
    #pragma unroll
    for (int it = 0; it < 4; ++it) {          // A: 256 rows x 8 x 16B
        int idx = tid + it * 512;
        int r = idx >> 3, c16 = idx & 7;
        cpa16(stage + T_A + sw128((uint32_t)(r * 128 + c16 * 16)),
              Ab + (size_t)r * KDIM + c16 * 8);
    }
    #pragma unroll
    for (int it = 0; it < 2; ++it) {          // B: 128 rows x 8 x 16B
        int idx = tid + it * 512;
        int r = idx >> 3, c16 = idx & 7;
        cpa16(stage + T_B + sw128((uint32_t)(r * 128 + c16 * 16)),
              Bb + (size_t)r * KDIM + c16 * 8);
    }
}

// Compute one K=64 chunk (4 k16 steps): warp tile 64(M) x 32(N).
// acc[mt][n8][4], mt in 0..3 (m16), n8 in 0..3.
__device__ __forceinline__ void compute_chunk(uint32_t stage_addr, int wm, int wn,
                                              int lane, float (&acc)[4][4][4]) {
    const uint32_t a_base = stage_addr + T_A;
    const uint32_t b_base = stage_addr + T_B;
    const int a_m = lane % 16;
    const int a_k = (lane / 16) * 8;
    const int b_n = (lane / 16) * 8 + (lane % 8);
    const int b_k = ((lane / 8) % 2) * 8;

    #pragma unroll
    for (int kk = 0; kk < 4; ++kk) {
        uint32_t Ah[4][4], Bh[2][4];
        #pragma unroll
        for (int mt = 0; mt < 4; ++mt) {
            uint32_t off = sw128((uint32_t)((wm + mt * 16 + a_m) * 128 + kk * 32 + a_k * 2));
            ldsm4(a_base + off, Ah[mt]);
        }
        #pragma unroll
        for (int nt = 0; nt < 2; ++nt) {
            uint32_t off = sw128((uint32_t)((wn + nt * 16 + b_n) * 128 + kk * 32 + b_k * 2));
            ldsm4(b_base + off, Bh[nt]);
        }
        #pragma unroll
        for (int mt = 0; mt < 4; ++mt)
            #pragma unroll
            for (int n8 = 0; n8 < 4; ++n8)
                mma16816(acc[mt][n8], Ah[mt], &Bh[n8 >> 1][(n8 & 1) * 2]);
    }
}

// ---------------------------------------------------------------------------
// fp32 -> fp16 converter (vectorized)
// ---------------------------------------------------------------------------
__global__ __launch_bounds__(256)
void f2h_kernel(const float4* __restrict__ in, uint2* __restrict__ out, int n4) {
    int i = blockIdx.x * blockDim.x + threadIdx.x;
    if (i >= n4) return;
    float4 v = in[i];
    __half2 h0 = __floats2half2_rn(v.x, v.y);
    __half2 h1 = __floats2half2_rn(v.z, v.w);
    out[i] = make_uint2(*reinterpret_cast<uint32_t*>(&h0),
                        *reinterpret_cast<uint32_t*>(&h1));
}

// ---------------------------------------------------------------------------
// GEMM1: gates[B, 8192] = x@w_ih^T + hx@w_hh^T (+ cx@w_p{i,f}^T) + biases
// grid = (16 m-tiles, 64 n-tiles), block = 512. CTA tile 256x128.
// ---------------------------------------------------------------------------
__global__ __launch_bounds__(512, 1)
void gemm_gates(const float* __restrict__ b_ih, const float* __restrict__ b_hh)
{
    extern __shared__ char sm[];
    const int tid  = threadIdx.x;
    const int wid  = tid >> 5;
    const int lane = tid & 31;
    const int m0   = blockIdx.x * 256;
    const int n0   = blockIdx.y * 128;
    const int wm   = (wid & 3) * 64;
    const int wn   = (wid >> 2) * 32;

    float* bsum = reinterpret_cast<float*>(sm);
    if (tid < 128) bsum[tid] = b_ih[n0 + tid] + b_hh[n0 + tid];

    const uint32_t smb = smem_u32(sm);
    const int nseg = (n0 < 2 * OUTF) ? 3 : 2;
    const __half* segA[3];
    const __half* segB[3];
    segA[0] = g_xh  + (size_t)m0 * KDIM; segB[0] = g_wih + (size_t)n0 * KDIM;
    segA[1] = g_hxh + (size_t)m0 * KDIM; segB[1] = g_whh + (size_t)n0 * KDIM;
    segA[2] = g_cxh + (size_t)m0 * KDIM; segB[2] = g_wp  + (size_t)n0 * KDIM;

    float acc[4][4][4];
    #pragma unroll
    for (int i = 0; i < 4; ++i)
        #pragma unroll
        for (int j = 0; j < 4; ++j)
            #pragma unroll
            for (int k = 0; k < 4; ++k) acc[i][j][k] = 0.f;

    const int nch = nseg * 32;

    load_chunk(segA[0], segB[0], smb + HDR, tid);
    CP_COMMIT();

    for (int c = 0; c < nch; ++c) {
        if (c + 1 < nch) {
            const int seg = (c + 1) >> 5;
            const int kc  = ((c + 1) & 31) << 6;
            load_chunk(segA[seg] + kc, segB[seg] + kc,
                       smb + HDR + ((c + 1) & 1) * STAGE_SZ, tid);
            CP_COMMIT();
            CP_WAIT1();
        } else {
            CP_WAIT0();
        }
        __syncthreads();
        compute_chunk(smb + HDR + (c & 1) * STAGE_SZ, wm, wn, lane, acc);
        __syncthreads();
    }

    // epilogue: bias + store fp32
    #pragma unroll
    for (int mt = 0; mt < 4; ++mt) {
        #pragma unroll
        for (int n8 = 0; n8 < 4; ++n8) {
            int lcol = wn + n8 * 8 + (lane % 4) * 2;
            float bx0 = bsum[lcol], bx1 = bsum[lcol + 1];
            int r0 = m0 + wm + mt * 16 + lane / 4;
            float* g0 = g_gates + (size_t)r0 * NG + n0 + lcol;
            float* g1 = g_gates + (size_t)(r0 + 8) * NG + n0 + lcol;
            *reinterpret_cast<float2*>(g0) =
                make_float2(acc[mt][n8][0] + bx0, acc[mt][n8][1] + bx1);
            *reinterpret_cast<float2*>(g1) =
                make_float2(acc[mt][n8][2] + bx0, acc[mt][n8][3] + bx1);
        }
    }
}

// ---------------------------------------------------------------------------
// Cell update: cy = a*exp(-b*td0)*sig(f)*cx + a*exp(-b*td1)*sig(i)*tanh(g)
// Writes cy fp32 (d_out) and cy fp16 (g_cyh).
// ---------------------------------------------------------------------------
__global__ __launch_bounds__(256)
void cell_kernel(const float* __restrict__ cx,
                 const float* __restrict__ td0, const float* __restrict__ td1,
                 const float* __restrict__ aS,  const float* __restrict__ bS,
                 float* __restrict__ cy_out)
{
    size_t idx4 = (size_t)blockIdx.x * blockDim.x + threadIdx.x;
    const size_t total4 = (size_t)BSZ * OUTF / 4;
    if (idx4 >= total4) return;
    int row = (int)(idx4 / (OUTF / 4));
    int c   = (int)(idx4 % (OUTF / 4)) * 4;

    float a = aS[0], b = bS[0];
    float forc = a * expf(-b * td0[row]);
    float inc  = a * expf(-b * td1[row]);

    const float* grow = g_gates + (size_t)row * NG;
    float4 ig  = *reinterpret_cast<const float4*>(grow + c);
    float4 fg  = *reinterpret_cast<const float4*>(grow + OUTF + c);
    float4 gg  = *reinterpret_cast<const float4*>(grow + 2 * OUTF + c);
    float4 cxv = *reinterpret_cast<const float4*>(cx + (size_t)row * OUTF + c);

    float4 r;
    r.x = forc * sigf(fg.x) * cxv.x + inc * sigf(ig.x) * tanhf(gg.x);
    r.y = forc * sigf(fg.y) * cxv.y + inc * sigf(ig.y) * tanhf(gg.y);
    r.z = forc * sigf(fg.z) * cxv.z + inc * sigf(ig.z) * tanhf(gg.z);
    r.w = forc * sigf(fg.w) * cxv.w + inc * sigf(ig.w) * tanhf(gg.w);
    *reinterpret_cast<float4*>(cy_out + (size_t)row * OUTF + c) = r;

    __half2 c0 = __floats2half2_rn(r.x, r.y);
    __half2 c1 = __floats2half2_rn(r.z, r.w);
    *reinterpret_cast<uint2*>(g_cyh + (size_t)row * OUTF + c) =
        make_uint2(*reinterpret_cast<uint32_t*>(&c0), *reinterpret_cast<uint32_t*>(&c1));
}

// ---------------------------------------------------------------------------
// GEMM3: O = cy @ w_po^T ; hy = sigmoid(gate_o + O) * tanh(cy)
// grid = (16 m-tiles, 16 n-tiles), block = 512. CTA tile 256x128.
// ---------------------------------------------------------------------------
__global__ __launch_bounds__(512, 1)
void gemm_out(const float* __restrict__ cy, float* __restrict__ hy)
{
    extern __shared__ char sm[];
    const int tid  = threadIdx.x;
    const int wid  = tid >> 5;
    const int lane = tid & 31;
    const int m0   = blockIdx.x * 256;
    const int n0   = blockIdx.y * 128;
    const int wm   = (wid & 3) * 64;
    const int wn   = (wid >> 2) * 32;

    const uint32_t smb = smem_u32(sm);
    const __half* Ab = g_cyh + (size_t)m0 * KDIM;
    const __half* Bb = g_wpo + (size_t)n0 * KDIM;

    float acc[4][4][4];
    #pragma unroll
    for (int i = 0; i < 4; ++i)
        #pragma unroll
        for (int j = 0; j < 4; ++j)
            #pragma unroll
            for (int k = 0; k < 4; ++k) acc[i][j][k] = 0.f;

    const int nch = 32;

    load_chunk(Ab, Bb, smb + HDR, tid);
    CP_COMMIT();

    for (int c = 0; c < nch; ++c) {
        if (c + 1 < nch) {
            const int kc = (c + 1) << 6;
            load_chunk(Ab + kc, Bb + kc, smb + HDR + ((c + 1) & 1) * STAGE_SZ, tid);
            CP_COMMIT();
            CP_WAIT1();
        } else {
            CP_WAIT0();
        }
        __syncthreads();
        compute_chunk(smb + HDR + (c & 1) * STAGE_SZ, wm, wn, lane, acc);
        __syncthreads();
    }

    // fused epilogue
    #pragma unroll
    for (int mt = 0; mt < 4; ++mt) {
        #pragma unroll
        for (int n8 = 0; n8 < 4; ++n8) {
            int col = n0 + wn + n8 * 8 + (lane % 4) * 2;
            #pragma unroll
            for (int half = 0; half < 2; ++half) {
                int row = m0 + wm + mt * 16 + lane / 4 + half * 8;
                const float* gorow = g_gates + (size_t)row * NG + 3 * OUTF + col;
                const float* cyrow = cy + (size_t)row * OUTF + col;
                float*       hyrow = hy + (size_t)row * OUTF + col;
                float2 go  = *reinterpret_cast<const float2*>(gorow);
                float2 cyv = *reinterpret_cast<const float2*>(cyrow);
                float2 r;
                r.x = sigf(go.x + acc[mt][n8][half * 2 + 0]) * tanhf(cyv.x);
                r.y = sigf(go.y + acc[mt][n8][half * 2 + 1]) * tanhf(cyv.y);
                *reinterpret_cast<float2*>(hyrow) = r;
            }
        }
    }
}

// ---------------------------------------------------------------------------
extern "C" void kernel_launch(void* const* d_in, const int* in_sizes, int n_in,
                              void* d_out, int out_size)
{
    (void)in_sizes; (void)n_in; (void)out_size;
    const float* x    = (const float*)d_in[0];
    const float* td0  = (const float*)d_in[1];
    const float* td1  = (const float*)d_in[2];
    const float* hx   = (const float*)d_in[3];
    const float* cx   = (const float*)d_in[4];
    const float* w_ih = (const float*)d_in[5];
    const float* w_hh = (const float*)d_in[6];
    const float* w_pi = (const float*)d_in[7];
    const float* w_pf = (const float*)d_in[8];
    const float* w_po = (const float*)d_in[9];
    const float* b_ih = (const float*)d_in[10];
    const float* b_hh = (const float*)d_in[11];
    const float* aS   = (const float*)d_in[12];
    const float* bS   = (const float*)d_in[13];

    float* out = (float*)d_out;
    float* hy  = out;                        // [B, OUT]
    float* cy  = out + (size_t)BSZ * OUTF;   // [B, OUT]

    // symbol addresses for fp16 buffers
    void *p_xh, *p_hxh, *p_cxh, *p_wih, *p_whh, *p_wp, *p_wpo;
    cudaGetSymbolAddress(&p_xh,  g_xh);
    cudaGetSymbolAddress(&p_hxh, g_hxh);
    cudaGetSymbolAddress(&p_cxh, g_cxh);
    cudaGetSymbolAddress(&p_wih, g_wih);
    cudaGetSymbolAddress(&p_whh, g_whh);
    cudaGetSymbolAddress(&p_wp,  g_wp);
    cudaGetSymbolAddress(&p_wpo, g_wpo);

    const int actN4 = BSZ * KDIM / 4;        // activations
    const int wBigN4 = NG * KDIM / 4;        // w_ih / w_hh
    const int wSmN4 = OUTF * KDIM / 4;       // peephole / output weights
    const int TB = 256;

    f2h_kernel<<<(actN4 + TB - 1) / TB, TB>>>((const float4*)x,  (uint2*)p_xh,  actN4);
    f2h_kernel<<<(actN4 + TB - 1) / TB, TB>>>((const float4*)hx, (uint2*)p_hxh, actN4);
    f2h_kernel<<<(actN4 + TB - 1) / TB, TB>>>((const float4*)cx, (uint2*)p_cxh, actN4);
    f2h_kernel<<<(wBigN4 + TB - 1) / TB, TB>>>((const float4*)w_ih, (uint2*)p_wih, wBigN4);
    f2h_kernel<<<(wBigN4 + TB - 1) / TB, TB>>>((const float4*)w_hh, (uint2*)p_whh, wBigN4);
    f2h_kernel<<<(wSmN4 + TB - 1) / TB, TB>>>((const float4*)w_pi, (uint2*)p_wp, wSmN4);
    f2h_kernel<<<(wSmN4 + TB - 1) / TB, TB>>>((const float4*)w_pf,
        (uint2*)((char*)p_wp + (size_t)OUTF * KDIM * sizeof(__half)), wSmN4);
    f2h_kernel<<<(wSmN4 + TB - 1) / TB, TB>>>((const float4*)w_po, (uint2*)p_wpo, wSmN4);

    cudaFuncSetAttribute(gemm_gates, cudaFuncAttributeMaxDynamicSharedMemorySize, SMEM_TOTAL);
    cudaFuncSetAttribute(gemm_out,   cudaFuncAttributeMaxDynamicSharedMemorySize, SMEM_TOTAL);

    gemm_gates<<<dim3(BSZ / 256, NG / 128), 512, SMEM_TOTAL>>>(b_ih, b_hh);

    cell_kernel<<<(BSZ * OUTF / 4 + 255) / 256, 256>>>(cx, td0, td1, aS, bS, cy);

    gemm_out<<<dim3(BSZ / 256, OUTF / 128), 512, SMEM_TOTAL>>>(cy, hy);
}

// round 7
// speedup vs baseline: 7.8382x; 1.0133x over previous
#include <cuda_runtime.h>
#include <cuda_fp16.h>
#include <cstdint>
#include <math.h>

#define BSZ  4096
#define OUTF 2048
#define NG   8192
#define KDIM 2048

// fp32 gate pre-activations scratch [B, 4*OUT]
__device__ float g_gates[(size_t)BSZ * NG];   // 128 MiB

// fp16 copies (filled by prologue converts / cell kernel)
__device__ __half g_xh [(size_t)BSZ * KDIM];
__device__ __half g_hxh[(size_t)BSZ * KDIM];
__device__ __half g_cxh[(size_t)BSZ * KDIM];
__device__ __half g_cyh[(size_t)BSZ * KDIM];
__device__ __half g_wih[(size_t)NG * KDIM];
__device__ __half g_whh[(size_t)NG * KDIM];
__device__ __half g_wp [(size_t)2 * OUTF * KDIM];   // w_pi rows then w_pf rows
__device__ __half g_wpo[(size_t)OUTF * KDIM];

__device__ __forceinline__ uint32_t smem_u32(const void* p) {
    uint32_t a;
    asm("{ .reg .u64 t; cvta.to.shared.u64 t, %1; cvt.u32.u64 %0, t; }" : "=r"(a) : "l"(p));
    return a;
}
__device__ __forceinline__ float sigf(float x) { return 1.0f / (1.0f + expf(-x)); }

__device__ __forceinline__ uint32_t sw128(uint32_t off) {
    return off ^ ((off >> 3) & 0x70);
}

__device__ __forceinline__ void ldsm4(uint32_t addr, uint32_t* r) {
    asm volatile("ldmatrix.sync.aligned.m8n8.x4.shared.b16 {%0,%1,%2,%3}, [%4];"
        : "=r"(r[0]), "=r"(r[1]), "=r"(r[2]), "=r"(r[3]) : "r"(addr));
}

__device__ __forceinline__ void mma16816(float* d, const uint32_t* a, const uint32_t* b) {
    asm volatile(
        "mma.sync.aligned.m16n8k16.row.col.f32.f16.f16.f32 "
        "{%0,%1,%2,%3}, {%4,%5,%6,%7}, {%8,%9}, {%0,%1,%2,%3};"
        : "+f"(d[0]), "+f"(d[1]), "+f"(d[2]), "+f"(d[3])
        : "r"(a[0]), "r"(a[1]), "r"(a[2]), "r"(a[3]), "r"(b[0]), "r"(b[1]));
}

__device__ __forceinline__ void cpa16(uint32_t dst, const void* src) {
    asm volatile("cp.async.cg.shared.global [%0], [%1], 16;" :: "r"(dst), "l"(src));
}
#define CP_COMMIT() asm volatile("cp.async.commit_group;" ::: "memory")
#define CP_WAIT1()  asm volatile("cp.async.wait_group 1;"  ::: "memory")
#define CP_WAIT0()  asm volatile("cp.async.wait_group 0;"  ::: "memory")

// ---------------- SMEM layout ----------------
// header 1024B: bias[128] floats (gates kernel only)
// stage (48KB): A 32KB (256 rows x 128B) | B 16KB (128 rows x 128B), fp16, SW128
// 3 stages for single-barrier pipeline.
#define HDR       1024
#define T_A       0
#define T_B       32768
#define STAGE_SZ  49152
#define NSTAGE    3
#define SMEM_TOTAL (HDR + NSTAGE * STAGE_SZ)   // 148480

// async-load one K=64 chunk: A 256 rows, B 128 rows (fp16 global, row stride KDIM)
__device__ __forceinline__ void load_chunk(const __half* __restrict__ Ab,
                                           const __half* __restrict__ Bb,
                                           uint32_t stage, int tid) {
    #pragma unroll
    for (int it = 0; it < 4; ++it) {          // A: 256 rows x 8 x 16B
        int idx = tid + it * 512;
        int r = idx >> 3, c16 = idx & 7;
        cpa16(stage + T_A + sw128((uint32_t)(r * 128 + c16 * 16)),
              Ab + (size_t)r * KDIM + c16 * 8);
    }
    #pragma unroll
    for (int it = 0; it < 2; ++it) {          // B: 128 rows x 8 x 16B
        int idx = tid + it * 512;
        int r = idx >> 3, c16 = idx & 7;
        cpa16(stage + T_B + sw128((uint32_t)(r * 128 + c16 * 16)),
              Bb + (size_t)r * KDIM + c16 * 8);
    }
}

// Compute one K=64 chunk (4 k16 steps): warp tile 64(M) x 32(N).
// acc[mt][n8][4], mt in 0..3 (m16), n8 in 0..3.
__device__ __forceinline__ void compute_chunk(uint32_t stage_addr, int wm, int wn,
                                              int lane, float (&acc)[4][4][4]) {
    const uint32_t a_base = stage_addr + T_A;
    const uint32_t b_base = stage_addr + T_B;
    const int a_m = lane % 16;
    const int a_k = (lane / 16) * 8;
    const int b_n = (lane / 16) * 8 + (lane % 8);
    const int b_k = ((lane / 8) % 2) * 8;

    #pragma unroll
    for (int kk = 0; kk < 4; ++kk) {
        uint32_t Ah[4][4], Bh[2][4];
        #pragma unroll
        for (int mt = 0; mt < 4; ++mt) {
            uint32_t off = sw128((uint32_t)((wm + mt * 16 + a_m) * 128 + kk * 32 + a_k * 2));
            ldsm4(a_base + off, Ah[mt]);
        }
        #pragma unroll
        for (int nt = 0; nt < 2; ++nt) {
            uint32_t off = sw128((uint32_t)((wn + nt * 16 + b_n) * 128 + kk * 32 + b_k * 2));
            ldsm4(b_base + off, Bh[nt]);
        }
        #pragma unroll
        for (int mt = 0; mt < 4; ++mt)
            #pragma unroll
            for (int n8 = 0; n8 < 4; ++n8)
                mma16816(acc[mt][n8], Ah[mt], &Bh[n8 >> 1][(n8 & 1) * 2]);
    }
}

// ---------------------------------------------------------------------------
// Merged fp32 -> fp16 converter: grid.y selects segment, grid-stride in x.
// ---------------------------------------------------------------------------
struct F2HSeg { const float4* src; uint2* dst; int n4; };

__global__ __launch_bounds__(256)
void f2h_all(F2HSeg s0, F2HSeg s1, F2HSeg s2, F2HSeg s3,
             F2HSeg s4, F2HSeg s5, F2HSeg s6, F2HSeg s7) {
    F2HSeg s;
    switch (blockIdx.y) {
        case 0: s = s0; break; case 1: s = s1; break;
        case 2: s = s2; break; case 3: s = s3; break;
        case 4: s = s4; break; case 5: s = s5; break;
        case 6: s = s6; break; default: s = s7; break;
    }
    const int stride = gridDim.x * blockDim.x;
    for (int i = blockIdx.x * blockDim.x + threadIdx.x; i < s.n4; i += stride) {
        float4 v = s.src[i];
        __half2 h0 = __floats2half2_rn(v.x, v.y);
        __half2 h1 = __floats2half2_rn(v.z, v.w);
        s.dst[i] = make_uint2(*reinterpret_cast<uint32_t*>(&h0),
                              *reinterpret_cast<uint32_t*>(&h1));
    }
}

// ---------------------------------------------------------------------------
// GEMM1: gates[B, 8192] = x@w_ih^T + hx@w_hh^T (+ cx@w_p{i,f}^T) + biases
// grid = (16 m-tiles, 64 n-tiles), block = 512. CTA tile 256x128.
// ---------------------------------------------------------------------------
__global__ __launch_bounds__(512, 1)
void gemm_gates(const float* __restrict__ b_ih, const float* __restrict__ b_hh)
{
    extern __shared__ char sm[];
    const int tid  = threadIdx.x;
    const int wid  = tid >> 5;
    const int lane = tid & 31;
    const int m0   = blockIdx.x * 256;
    const int n0   = blockIdx.y * 128;
    const int wm   = (wid & 3) * 64;
    const int wn   = (wid >> 2) * 32;

    float* bsum = reinterpret_cast<float*>(sm);
    if (tid < 128) bsum[tid] = b_ih[n0 + tid] + b_hh[n0 + tid];

    const uint32_t smb = smem_u32(sm);
    const int nseg = (n0 < 2 * OUTF) ? 3 : 2;
    const __half* segA[3];
    const __half* segB[3];
    segA[0] = g_xh  + (size_t)m0 * KDIM; segB[0] = g_wih + (size_t)n0 * KDIM;
    segA[1] = g_hxh + (size_t)m0 * KDIM; segB[1] = g_whh + (size_t)n0 * KDIM;
    segA[2] = g_cxh + (size_t)m0 * KDIM; segB[2] = g_wp  + (size_t)n0 * KDIM;

    float acc[4][4][4];
    #pragma unroll
    for (int i = 0; i < 4; ++i)
        #pragma unroll
        for (int j = 0; j < 4; ++j)
            #pragma unroll
            for (int k = 0; k < 4; ++k) acc[i][j][k] = 0.f;

    const int nch = nseg * 32;

    auto issue = [&](int c) {
        const int seg = c >> 5;
        const int kc  = (c & 31) << 6;
        load_chunk(segA[seg] + kc, segB[seg] + kc,
                   smb + HDR + (uint32_t)(c % NSTAGE) * STAGE_SZ, tid);
        CP_COMMIT();
    };

    issue(0);
    issue(1);

    for (int c = 0; c < nch; ++c) {
        if (c + 1 < nch) { CP_WAIT1(); } else { CP_WAIT0(); }
        __syncthreads();
        if (c + 2 < nch) issue(c + 2);
        compute_chunk(smb + HDR + (uint32_t)(c % NSTAGE) * STAGE_SZ, wm, wn, lane, acc);
    }

    // epilogue: bias + store fp32
    #pragma unroll
    for (int mt = 0; mt < 4; ++mt) {
        #pragma unroll
        for (int n8 = 0; n8 < 4; ++n8) {
            int lcol = wn + n8 * 8 + (lane % 4) * 2;
            float bx0 = bsum[lcol], bx1 = bsum[lcol + 1];
            int r0 = m0 + wm + mt * 16 + lane / 4;
            float* g0 = g_gates + (size_t)r0 * NG + n0 + lcol;
            float* g1 = g_gates + (size_t)(r0 + 8) * NG + n0 + lcol;
            *reinterpret_cast<float2*>(g0) =
                make_float2(acc[mt][n8][0] + bx0, acc[mt][n8][1] + bx1);
            *reinterpret_cast<float2*>(g1) =
                make_float2(acc[mt][n8][2] + bx0, acc[mt][n8][3] + bx1);
        }
    }
}

// ---------------------------------------------------------------------------
// Cell update: cy = a*exp(-b*td0)*sig(f)*cx + a*exp(-b*td1)*sig(i)*tanh(g)
// Writes cy fp32 (d_out) and cy fp16 (g_cyh).
// ---------------------------------------------------------------------------
__global__ __launch_bounds__(256)
void cell_kernel(const float* __restrict__ cx,
                 const float* __restrict__ td0, const float* __restrict__ td1,
                 const float* __restrict__ aS,  const float* __restrict__ bS,
                 float* __restrict__ cy_out)
{
    size_t idx4 = (size_t)blockIdx.x * blockDim.x + threadIdx.x;
    const size_t total4 = (size_t)BSZ * OUTF / 4;
    if (idx4 >= total4) return;
    int row = (int)(idx4 / (OUTF / 4));
    int c   = (int)(idx4 % (OUTF / 4)) * 4;

    float a = aS[0], b = bS[0];
    float forc = a * expf(-b * td0[row]);
    float inc  = a * expf(-b * td1[row]);

    const float* grow = g_gates + (size_t)row * NG;
    float4 ig  = *reinterpret_cast<const float4*>(grow + c);
    float4 fg  = *reinterpret_cast<const float4*>(grow + OUTF + c);
    float4 gg  = *reinterpret_cast<const float4*>(grow + 2 * OUTF + c);
    float4 cxv = *reinterpret_cast<const float4*>(cx + (size_t)row * OUTF + c);

    float4 r;
    r.x = forc * sigf(fg.x) * cxv.x + inc * sigf(ig.x) * tanhf(gg.x);
    r.y = forc * sigf(fg.y) * cxv.y + inc * sigf(ig.y) * tanhf(gg.y);
    r.z = forc * sigf(fg.z) * cxv.z + inc * sigf(ig.z) * tanhf(gg.z);
    r.w = forc * sigf(fg.w) * cxv.w + inc * sigf(ig.w) * tanhf(gg.w);
    *reinterpret_cast<float4*>(cy_out + (size_t)row * OUTF + c) = r;

    __half2 c0 = __floats2half2_rn(r.x, r.y);
    __half2 c1 = __floats2half2_rn(r.z, r.w);
    *reinterpret_cast<uint2*>(g_cyh + (size_t)row * OUTF + c) =
        make_uint2(*reinterpret_cast<uint32_t*>(&c0), *reinterpret_cast<uint32_t*>(&c1));
}

// ---------------------------------------------------------------------------
// GEMM3: O = cy @ w_po^T ; hy = sigmoid(gate_o + O) * tanh(cy)
// grid = (16 m-tiles, 16 n-tiles), block = 512. CTA tile 256x128.
// ---------------------------------------------------------------------------
__global__ __launch_bounds__(512, 1)
void gemm_out(const float* __restrict__ cy, float* __restrict__ hy)
{
    extern __shared__ char sm[];
    const int tid  = threadIdx.x;
    const int wid  = tid >> 5;
    const int lane = tid & 31;
    const int m0   = blockIdx.x * 256;
    const int n0   = blockIdx.y * 128;
    const int wm   = (wid & 3) * 64;
    const int wn   = (wid >> 2) * 32;

    const uint32_t smb = smem_u32(sm);
    const __half* Ab = g_cyh + (size_t)m0 * KDIM;
    const __half* Bb = g_wpo + (size_t)n0 * KDIM;

    float acc[4][4][4];
    #pragma unroll
    for (int i = 0; i < 4; ++i)
        #pragma unroll
        for (int j = 0; j < 4; ++j)
            #pragma unroll
            for (int k = 0; k < 4; ++k) acc[i][j][k] = 0.f;

    const int nch = 32;

    auto issue = [&](int c) {
        const int kc = c << 6;
        load_chunk(Ab + kc, Bb + kc,
                   smb + HDR + (uint32_t)(c % NSTAGE) * STAGE_SZ, tid);
        CP_COMMIT();
    };

    issue(0);
    issue(1);

    for (int c = 0; c < nch; ++c) {
        if (c + 1 < nch) { CP_WAIT1(); } else { CP_WAIT0(); }
        __syncthreads();
        if (c + 2 < nch) issue(c + 2);
        compute_chunk(smb + HDR + (uint32_t)(c % NSTAGE) * STAGE_SZ, wm, wn, lane, acc);
    }

    // fused epilogue
    #pragma unroll
    for (int mt = 0; mt < 4; ++mt) {
        #pragma unroll
        for (int n8 = 0; n8 < 4; ++n8) {
            int col = n0 + wn + n8 * 8 + (lane % 4) * 2;
            #pragma unroll
            for (int half = 0; half < 2; ++half) {
                int row = m0 + wm + mt * 16 + lane / 4 + half * 8;
                const float* gorow = g_gates + (size_t)row * NG + 3 * OUTF + col;
                const float* cyrow = cy + (size_t)row * OUTF + col;
                float*       hyrow = hy + (size_t)row * OUTF + col;
                float2 go  = *reinterpret_cast<const float2*>(gorow);
                float2 cyv = *reinterpret_cast<const float2*>(cyrow);
                float2 r;
                r.x = sigf(go.x + acc[mt][n8][half * 2 + 0]) * tanhf(cyv.x);
                r.y = sigf(go.y + acc[mt][n8][half * 2 + 1]) * tanhf(cyv.y);
                *reinterpret_cast<float2*>(hyrow) = r;
            }
        }
    }
}

// ---------------------------------------------------------------------------
extern "C" void kernel_launch(void* const* d_in, const int* in_sizes, int n_in,
                              void* d_out, int out_size)
{
    (void)in_sizes; (void)n_in; (void)out_size;
    const float* x    = (const float*)d_in[0];
    const float* td0  = (const float*)d_in[1];
    const float* td1  = (const float*)d_in[2];
    const float* hx   = (const float*)d_in[3];
    const float* cx   = (const float*)d_in[4];
    const float* w_ih = (const float*)d_in[5];
    const float* w_hh = (const float*)d_in[6];
    const float* w_pi = (const float*)d_in[7];
    const float* w_pf = (const float*)d_in[8];
    const float* w_po = (const float*)d_in[9];
    const float* b_ih = (const float*)d_in[10];
    const float* b_hh = (const float*)d_in[11];
    const float* aS   = (const float*)d_in[12];
    const float* bS   = (const float*)d_in[13];

    float* out = (float*)d_out;
    float* hy  = out;                        // [B, OUT]
    float* cy  = out + (size_t)BSZ * OUTF;   // [B, OUT]

    // symbol addresses for fp16 buffers
    void *p_xh, *p_hxh, *p_cxh, *p_wih, *p_whh, *p_wp, *p_wpo;
    cudaGetSymbolAddress(&p_xh,  g_xh);
    cudaGetSymbolAddress(&p_hxh, g_hxh);
    cudaGetSymbolAddress(&p_cxh, g_cxh);
    cudaGetSymbolAddress(&p_wih, g_wih);
    cudaGetSymbolAddress(&p_whh, g_whh);
    cudaGetSymbolAddress(&p_wp,  g_wp);
    cudaGetSymbolAddress(&p_wpo, g_wpo);

    const int actN4 = BSZ * KDIM / 4;        // activations
    const int wBigN4 = NG * KDIM / 4;        // w_ih / w_hh
    const int wSmN4 = OUTF * KDIM / 4;       // peephole / output weights

    F2HSeg s0 = {(const float4*)x,    (uint2*)p_xh,  actN4};
    F2HSeg s1 = {(const float4*)hx,   (uint2*)p_hxh, actN4};
    F2HSeg s2 = {(const float4*)cx,   (uint2*)p_cxh, actN4};
    F2HSeg s3 = {(const float4*)w_ih, (uint2*)p_wih, wBigN4};
    F2HSeg s4 = {(const float4*)w_hh, (uint2*)p_whh, wBigN4};
    F2HSeg s5 = {(const float4*)w_pi, (uint2*)p_wp,  wSmN4};
    F2HSeg s6 = {(const float4*)w_pf,
                 (uint2*)((char*)p_wp + (size_t)OUTF * KDIM * sizeof(__half)), wSmN4};
    F2HSeg s7 = {(const float4*)w_po, (uint2*)p_wpo, wSmN4};

    f2h_all<<<dim3(1024, 8), 256>>>(s0, s1, s2, s3, s4, s5, s6, s7);

    cudaFuncSetAttribute(gemm_gates, cudaFuncAttributeMaxDynamicSharedMemorySize, SMEM_TOTAL);
    cudaFuncSetAttribute(gemm_out,   cudaFuncAttributeMaxDynamicSharedMemorySize, SMEM_TOTAL);

    gemm_gates<<<dim3(BSZ / 256, NG / 128), 512, SMEM_TOTAL>>>(b_ih, b_hh);

    cell_kernel<<<(BSZ * OUTF / 4 + 255) / 256, 256>>>(cx, td0, td1, aS, bS, cy);

    gemm_out<<<dim3(BSZ / 256, OUTF / 128), 512, SMEM_TOTAL>>>(cy, hy);
}

// round 8
// speedup vs baseline: 8.5364x; 1.0891x over previous
#include <cuda_runtime.h>
#include <cuda_fp16.h>
#include <cstdint>
#include <math.h>

#define BSZ  4096
#define OUTF 2048
#define NG   8192
#define KDIM 2048

// fp32 gate pre-activations scratch [B, 4*OUT]
__device__ float g_gates[(size_t)BSZ * NG];   // 128 MiB

// fp16 copies (filled by prologue converts / cell kernel)
__device__ __half g_xh [(size_t)BSZ * KDIM];
__device__ __half g_hxh[(size_t)BSZ * KDIM];
__device__ __half g_cxh[(size_t)BSZ * KDIM];
__device__ __half g_cyh[(size_t)BSZ * KDIM];
__device__ __half g_wih[(size_t)NG * KDIM];
__device__ __half g_whh[(size_t)NG * KDIM];
__device__ __half g_wp [(size_t)2 * OUTF * KDIM];   // w_pi rows then w_pf rows
__device__ __half g_wpo[(size_t)OUTF * KDIM];

__device__ __forceinline__ uint32_t smem_u32(const void* p) {
    uint32_t a;
    asm("{ .reg .u64 t; cvta.to.shared.u64 t, %1; cvt.u32.u64 %0, t; }" : "=r"(a) : "l"(p));
    return a;
}
__device__ __forceinline__ float sigf(float x) { return 1.0f / (1.0f + expf(-x)); }

__device__ __forceinline__ uint32_t sw128(uint32_t off) {
    return off ^ ((off >> 3) & 0x70);
}

__device__ __forceinline__ void ldsm4(uint32_t addr, uint32_t* r) {
    asm volatile("ldmatrix.sync.aligned.m8n8.x4.shared.b16 {%0,%1,%2,%3}, [%4];"
        : "=r"(r[0]), "=r"(r[1]), "=r"(r[2]), "=r"(r[3]) : "r"(addr));
}

__device__ __forceinline__ void mma16816(float* d, const uint32_t* a, const uint32_t* b) {
    asm volatile(
        "mma.sync.aligned.m16n8k16.row.col.f32.f16.f16.f32 "
        "{%0,%1,%2,%3}, {%4,%5,%6,%7}, {%8,%9}, {%0,%1,%2,%3};"
        : "+f"(d[0]), "+f"(d[1]), "+f"(d[2]), "+f"(d[3])
        : "r"(a[0]), "r"(a[1]), "r"(a[2]), "r"(a[3]), "r"(b[0]), "r"(b[1]));
}

__device__ __forceinline__ void cpa16(uint32_t dst, const void* src) {
    asm volatile("cp.async.cg.shared.global [%0], [%1], 16;" :: "r"(dst), "l"(src));
}
#define CP_COMMIT() asm volatile("cp.async.commit_group;" ::: "memory")
#define CP_WAIT1()  asm volatile("cp.async.wait_group 1;"  ::: "memory")
#define CP_WAIT0()  asm volatile("cp.async.wait_group 0;"  ::: "memory")

// ---------------- SMEM layout ----------------
// header 1024B: bias[128] floats (gates kernel only)
// stage (32KB): A 16KB (128 rows x 128B) | B 16KB (128 rows x 128B), fp16, SW128
// 3 stages; 97KB/CTA -> 2 CTAs per SM.
#define HDR       1024
#define T_A       0
#define T_B       16384
#define STAGE_SZ  32768
#define NSTAGE    3
#define SMEM_TOTAL (HDR + NSTAGE * STAGE_SZ)   // 99328

// async-load one K=64 chunk: A 128 rows, B 128 rows (fp16 global, row stride KDIM)
// 256 threads: 8 x 16B per thread.
__device__ __forceinline__ void load_chunk(const __half* __restrict__ Ab,
                                           const __half* __restrict__ Bb,
                                           uint32_t stage, int tid) {
    #pragma unroll
    for (int it = 0; it < 4; ++it) {          // A: 128 rows x 8 x 16B
        int idx = tid + it * 256;
        int r = idx >> 3, c16 = idx & 7;
        cpa16(stage + T_A + sw128((uint32_t)(r * 128 + c16 * 16)),
              Ab + (size_t)r * KDIM + c16 * 8);
    }
    #pragma unroll
    for (int it = 0; it < 4; ++it) {          // B: 128 rows x 8 x 16B
        int idx = tid + it * 256;
        int r = idx >> 3, c16 = idx & 7;
        cpa16(stage + T_B + sw128((uint32_t)(r * 128 + c16 * 16)),
              Bb + (size_t)r * KDIM + c16 * 8);
    }
}

// Compute one K=64 chunk (4 k16 steps): warp tile 64(M) x 32(N).
// acc[mt][n8][4], mt in 0..3 (m16), n8 in 0..3.
__device__ __forceinline__ void compute_chunk(uint32_t stage_addr, int wm, int wn,
                                              int lane, float (&acc)[4][4][4]) {
    const uint32_t a_base = stage_addr + T_A;
    const uint32_t b_base = stage_addr + T_B;
    const int a_m = lane % 16;
    const int a_k = (lane / 16) * 8;
    const int b_n = (lane / 16) * 8 + (lane % 8);
    const int b_k = ((lane / 8) % 2) * 8;

    #pragma unroll
    for (int kk = 0; kk < 4; ++kk) {
        uint32_t Ah[4][4], Bh[2][4];
        #pragma unroll
        for (int mt = 0; mt < 4; ++mt) {
            uint32_t off = sw128((uint32_t)((wm + mt * 16 + a_m) * 128 + kk * 32 + a_k * 2));
            ldsm4(a_base + off, Ah[mt]);
        }
        #pragma unroll
        for (int nt = 0; nt < 2; ++nt) {
            uint32_t off = sw128((uint32_t)((wn + nt * 16 + b_n) * 128 + kk * 32 + b_k * 2));
            ldsm4(b_base + off, Bh[nt]);
        }
        #pragma unroll
        for (int mt = 0; mt < 4; ++mt)
            #pragma unroll
            for (int n8 = 0; n8 < 4; ++n8)
                mma16816(acc[mt][n8], Ah[mt], &Bh[n8 >> 1][(n8 & 1) * 2]);
    }
}

// ---------------------------------------------------------------------------
// Merged fp32 -> fp16 converter: grid.y selects segment, grid-stride in x.
// ---------------------------------------------------------------------------
struct F2HSeg { const float4* src; uint2* dst; int n4; };

__global__ __launch_bounds__(256)
void f2h_all(F2HSeg s0, F2HSeg s1, F2HSeg s2, F2HSeg s3,
             F2HSeg s4, F2HSeg s5, F2HSeg s6, F2HSeg s7) {
    F2HSeg s;
    switch (blockIdx.y) {
        case 0: s = s0; break; case 1: s = s1; break;
        case 2: s = s2; break; case 3: s = s3; break;
        case 4: s = s4; break; case 5: s = s5; break;
        case 6: s = s6; break; default: s = s7; break;
    }
    const int stride = gridDim.x * blockDim.x;
    for (int i = blockIdx.x * blockDim.x + threadIdx.x; i < s.n4; i += stride) {
        float4 v = s.src[i];
        __half2 h0 = __floats2half2_rn(v.x, v.y);
        __half2 h1 = __floats2half2_rn(v.z, v.w);
        s.dst[i] = make_uint2(*reinterpret_cast<uint32_t*>(&h0),
                              *reinterpret_cast<uint32_t*>(&h1));
    }
}

// ---------------------------------------------------------------------------
// GEMM1: gates[B, 8192] = x@w_ih^T + hx@w_hh^T (+ cx@w_p{i,f}^T) + biases
// grid = (32 m-tiles, 64 n-tiles), block = 256. CTA tile 128x128, 2 CTAs/SM.
// ---------------------------------------------------------------------------
__global__ __launch_bounds__(256, 2)
void gemm_gates(const float* __restrict__ b_ih, const float* __restrict__ b_hh)
{
    extern __shared__ char sm[];
    const int tid  = threadIdx.x;
    const int wid  = tid >> 5;
    const int lane = tid & 31;
    const int m0   = blockIdx.x * 128;
    const int n0   = blockIdx.y * 128;
    const int wm   = (wid & 1) * 64;
    const int wn   = (wid >> 1) * 32;

    float* bsum = reinterpret_cast<float*>(sm);
    if (tid < 128) bsum[tid] = b_ih[n0 + tid] + b_hh[n0 + tid];

    const uint32_t smb = smem_u32(sm);
    const int nseg = (n0 < 2 * OUTF) ? 3 : 2;
    const __half* segA[3];
    const __half* segB[3];
    segA[0] = g_xh  + (size_t)m0 * KDIM; segB[0] = g_wih + (size_t)n0 * KDIM;
    segA[1] = g_hxh + (size_t)m0 * KDIM; segB[1] = g_whh + (size_t)n0 * KDIM;
    segA[2] = g_cxh + (size_t)m0 * KDIM; segB[2] = g_wp  + (size_t)n0 * KDIM;

    float acc[4][4][4];
    #pragma unroll
    for (int i = 0; i < 4; ++i)
        #pragma unroll
        for (int j = 0; j < 4; ++j)
            #pragma unroll
            for (int k = 0; k < 4; ++k) acc[i][j][k] = 0.f;

    const int nch = nseg * 32;

    auto issue = [&](int c) {
        const int seg = c >> 5;
        const int kc  = (c & 31) << 6;
        load_chunk(segA[seg] + kc, segB[seg] + kc,
                   smb + HDR + (uint32_t)(c % NSTAGE) * STAGE_SZ, tid);
        CP_COMMIT();
    };

    issue(0);
    issue(1);

    for (int c = 0; c < nch; ++c) {
        if (c + 1 < nch) { CP_WAIT1(); } else { CP_WAIT0(); }
        __syncthreads();
        if (c + 2 < nch) issue(c + 2);
        compute_chunk(smb + HDR + (uint32_t)(c % NSTAGE) * STAGE_SZ, wm, wn, lane, acc);
    }

    // epilogue: bias + store fp32
    #pragma unroll
    for (int mt = 0; mt < 4; ++mt) {
        #pragma unroll
        for (int n8 = 0; n8 < 4; ++n8) {
            int lcol = wn + n8 * 8 + (lane % 4) * 2;
            float bx0 = bsum[lcol], bx1 = bsum[lcol + 1];
            int r0 = m0 + wm + mt * 16 + lane / 4;
            float* g0 = g_gates + (size_t)r0 * NG + n0 + lcol;
            float* g1 = g_gates + (size_t)(r0 + 8) * NG + n0 + lcol;
            *reinterpret_cast<float2*>(g0) =
                make_float2(acc[mt][n8][0] + bx0, acc[mt][n8][1] + bx1);
            *reinterpret_cast<float2*>(g1) =
                make_float2(acc[mt][n8][2] + bx0, acc[mt][n8][3] + bx1);
        }
    }
}

// ---------------------------------------------------------------------------
// Cell update: cy = a*exp(-b*td0)*sig(f)*cx + a*exp(-b*td1)*sig(i)*tanh(g)
// Writes cy fp32 (d_out) and cy fp16 (g_cyh).
// ---------------------------------------------------------------------------
__global__ __launch_bounds__(256)
void cell_kernel(const float* __restrict__ cx,
                 const float* __restrict__ td0, const float* __restrict__ td1,
                 const float* __restrict__ aS,  const float* __restrict__ bS,
                 float* __restrict__ cy_out)
{
    size_t idx4 = (size_t)blockIdx.x * blockDim.x + threadIdx.x;
    const size_t total4 = (size_t)BSZ * OUTF / 4;
    if (idx4 >= total4) return;
    int row = (int)(idx4 / (OUTF / 4));
    int c   = (int)(idx4 % (OUTF / 4)) * 4;

    float a = aS[0], b = bS[0];
    float forc = a * expf(-b * td0[row]);
    float inc  = a * expf(-b * td1[row]);

    const float* grow = g_gates + (size_t)row * NG;
    float4 ig  = *reinterpret_cast<const float4*>(grow + c);
    float4 fg  = *reinterpret_cast<const float4*>(grow + OUTF + c);
    float4 gg  = *reinterpret_cast<const float4*>(grow + 2 * OUTF + c);
    float4 cxv = *reinterpret_cast<const float4*>(cx + (size_t)row * OUTF + c);

    float4 r;
    r.x = forc * sigf(fg.x) * cxv.x + inc * sigf(ig.x) * tanhf(gg.x);
    r.y = forc * sigf(fg.y) * cxv.y + inc * sigf(ig.y) * tanhf(gg.y);
    r.z = forc * sigf(fg.z) * cxv.z + inc * sigf(ig.z) * tanhf(gg.z);
    r.w = forc * sigf(fg.w) * cxv.w + inc * sigf(ig.w) * tanhf(gg.w);
    *reinterpret_cast<float4*>(cy_out + (size_t)row * OUTF + c) = r;

    __half2 c0 = __floats2half2_rn(r.x, r.y);
    __half2 c1 = __floats2half2_rn(r.z, r.w);
    *reinterpret_cast<uint2*>(g_cyh + (size_t)row * OUTF + c) =
        make_uint2(*reinterpret_cast<uint32_t*>(&c0), *reinterpret_cast<uint32_t*>(&c1));
}

// ---------------------------------------------------------------------------
// GEMM3: O = cy @ w_po^T ; hy = sigmoid(gate_o + O) * tanh(cy)
// grid = (32 m-tiles, 16 n-tiles), block = 256. CTA tile 128x128, 2 CTAs/SM.
// ---------------------------------------------------------------------------
__global__ __launch_bounds__(256, 2)
void gemm_out(const float* __restrict__ cy, float* __restrict__ hy)
{
    extern __shared__ char sm[];
    const int tid  = threadIdx.x;
    const int wid  = tid >> 5;
    const int lane = tid & 31;
    const int m0   = blockIdx.x * 128;
    const int n0   = blockIdx.y * 128;
    const int wm   = (wid & 1) * 64;
    const int wn   = (wid >> 1) * 32;

    const uint32_t smb = smem_u32(sm);
    const __half* Ab = g_cyh + (size_t)m0 * KDIM;
    const __half* Bb = g_wpo + (size_t)n0 * KDIM;

    float acc[4][4][4];
    #pragma unroll
    for (int i = 0; i < 4; ++i)
        #pragma unroll
        for (int j = 0; j < 4; ++j)
            #pragma unroll
            for (int k = 0; k < 4; ++k) acc[i][j][k] = 0.f;

    const int nch = 32;

    auto issue = [&](int c) {
        const int kc = c << 6;
        load_chunk(Ab + kc, Bb + kc,
                   smb + HDR + (uint32_t)(c % NSTAGE) * STAGE_SZ, tid);
        CP_COMMIT();
    };

    issue(0);
    issue(1);

    for (int c = 0; c < nch; ++c) {
        if (c + 1 < nch) { CP_WAIT1(); } else { CP_WAIT0(); }
        __syncthreads();
        if (c + 2 < nch) issue(c + 2);
        compute_chunk(smb + HDR + (uint32_t)(c % NSTAGE) * STAGE_SZ, wm, wn, lane, acc);
    }

    // fused epilogue
    #pragma unroll
    for (int mt = 0; mt < 4; ++mt) {
        #pragma unroll
        for (int n8 = 0; n8 < 4; ++n8) {
            int col = n0 + wn + n8 * 8 + (lane % 4) * 2;
            #pragma unroll
            for (int half = 0; half < 2; ++half) {
                int row = m0 + wm + mt * 16 + lane / 4 + half * 8;
                const float* gorow = g_gates + (size_t)row * NG + 3 * OUTF + col;
                const float* cyrow = cy + (size_t)row * OUTF + col;
                float*       hyrow = hy + (size_t)row * OUTF + col;
                float2 go  = *reinterpret_cast<const float2*>(gorow);
                float2 cyv = *reinterpret_cast<const float2*>(cyrow);
                float2 r;
                r.x = sigf(go.x + acc[mt][n8][half * 2 + 0]) * tanhf(cyv.x);
                r.y = sigf(go.y + acc[mt][n8][half * 2 + 1]) * tanhf(cyv.y);
                *reinterpret_cast<float2*>(hyrow) = r;
            }
        }
    }
}

// ---------------------------------------------------------------------------
extern "C" void kernel_launch(void* const* d_in, const int* in_sizes, int n_in,
                              void* d_out, int out_size)
{
    (void)in_sizes; (void)n_in; (void)out_size;
    const float* x    = (const float*)d_in[0];
    const float* td0  = (const float*)d_in[1];
    const float* td1  = (const float*)d_in[2];
    const float* hx   = (const float*)d_in[3];
    const float* cx   = (const float*)d_in[4];
    const float* w_ih = (const float*)d_in[5];
    const float* w_hh = (const float*)d_in[6];
    const float* w_pi = (const float*)d_in[7];
    const float* w_pf = (const float*)d_in[8];
    const float* w_po = (const float*)d_in[9];
    const float* b_ih = (const float*)d_in[10];
    const float* b_hh = (const float*)d_in[11];
    const float* aS   = (const float*)d_in[12];
    const float* bS   = (const float*)d_in[13];

    float* out = (float*)d_out;
    float* hy  = out;                        // [B, OUT]
    float* cy  = out + (size_t)BSZ * OUTF;   // [B, OUT]

    // symbol addresses for fp16 buffers
    void *p_xh, *p_hxh, *p_cxh, *p_wih, *p_whh, *p_wp, *p_wpo;
    cudaGetSymbolAddress(&p_xh,  g_xh);
    cudaGetSymbolAddress(&p_hxh, g_hxh);
    cudaGetSymbolAddress(&p_cxh, g_cxh);
    cudaGetSymbolAddress(&p_wih, g_wih);
    cudaGetSymbolAddress(&p_whh, g_whh);
    cudaGetSymbolAddress(&p_wp,  g_wp);
    cudaGetSymbolAddress(&p_wpo, g_wpo);

    const int actN4 = BSZ * KDIM / 4;        // activations
    const int wBigN4 = NG * KDIM / 4;        // w_ih / w_hh
    const int wSmN4 = OUTF * KDIM / 4;       // peephole / output weights

    F2HSeg s0 = {(const float4*)x,    (uint2*)p_xh,  actN4};
    F2HSeg s1 = {(const float4*)hx,   (uint2*)p_hxh, actN4};
    F2HSeg s2 = {(const float4*)cx,   (uint2*)p_cxh, actN4};
    F2HSeg s3 = {(const float4*)w_ih, (uint2*)p_wih, wBigN4};
    F2HSeg s4 = {(const float4*)w_hh, (uint2*)p_whh, wBigN4};
    F2HSeg s5 = {(const float4*)w_pi, (uint2*)p_wp,  wSmN4};
    F2HSeg s6 = {(const float4*)w_pf,
                 (uint2*)((char*)p_wp + (size_t)OUTF * KDIM * sizeof(__half)), wSmN4};
    F2HSeg s7 = {(const float4*)w_po, (uint2*)p_wpo, wSmN4};

    f2h_all<<<dim3(1024, 8), 256>>>(s0, s1, s2, s3, s4, s5, s6, s7);

    cudaFuncSetAttribute(gemm_gates, cudaFuncAttributeMaxDynamicSharedMemorySize, SMEM_TOTAL);
    cudaFuncSetAttribute(gemm_out,   cudaFuncAttributeMaxDynamicSharedMemorySize, SMEM_TOTAL);

    gemm_gates<<<dim3(BSZ / 128, NG / 128), 256, SMEM_TOTAL>>>(b_ih, b_hh);

    cell_kernel<<<(BSZ * OUTF / 4 + 255) / 256, 256>>>(cx, td0, td1, aS, bS, cy);

    gemm_out<<<dim3(BSZ / 128, OUTF / 128), 256, SMEM_TOTAL>>>(cy, hy);
}